// round 1
// baseline (speedup 1.0000x reference)
#include <cuda_runtime.h>
#include <math.h>

// Problem constants
#define H 1024
#define W 1024
#define PLANE_SZ (H * W)
#define NPLANE 16                 // 8 planes for probs chain, 8 for target chain
#define HALF (8 * PLANE_SZ)       // 8M elements per tensor
#define TOTAL (NPLANE * PLANE_SZ) // 16M

#define N_STEPS 11                // init (k=0) + 10 loop iterations

// Tile config for the fused erode+dilate+skel step
#define TX 128
#define TY 16
#define STEP_THREADS 256

// -------- device scratch (no allocations allowed in kernel_launch) --------
__device__ float g_buf0[TOTAL];   // ping
__device__ float g_buf1[TOTAL];   // pong
__device__ float g_sk[TOTAL];     // skeleton accumulators
__device__ double g_acc[6];       // [0]=inter [1]=card [2]=sum_t  [3]=s_ot [4]=s_o [5]=s_tskel

// ---------------------------------------------------------------------------
__device__ __forceinline__ float blockReduceSum(float v, float* red) {
    #pragma unroll
    for (int o = 16; o > 0; o >>= 1) v += __shfl_down_sync(0xffffffffu, v, o);
    int lane = threadIdx.x & 31;
    int wid  = threadIdx.x >> 5;
    if (lane == 0) red[wid] = v;
    __syncthreads();
    int nwarp = blockDim.x >> 5;
    v = (threadIdx.x < nwarp) ? red[threadIdx.x] : 0.0f;
    if (wid == 0) {
        #pragma unroll
        for (int o = 16; o > 0; o >>= 1) v += __shfl_down_sync(0xffffffffu, v, o);
    }
    __syncthreads();
    return v;
}

// ---------------------------------------------------------------------------
__global__ void zero_acc_kernel() {
    if (threadIdx.x < 6) g_acc[threadIdx.x] = 0.0;
}

// sigmoid + cast + sk zero + dice sums
__global__ void init_kernel(const float* __restrict__ logits,
                            const int* __restrict__ target) {
    __shared__ float red[32];
    int tid = blockIdx.x * blockDim.x + threadIdx.x;
    int stride = gridDim.x * blockDim.x;
    float inter = 0.0f, card = 0.0f, st = 0.0f;
    for (int i = tid; i < HALF; i += stride) {
        float x = logits[i];
        float p = 1.0f / (1.0f + expf(-x));
        float t = (float)target[i];
        g_buf0[i]         = p;
        g_buf0[HALF + i]  = t;
        g_sk[i]           = 0.0f;
        g_sk[HALF + i]    = 0.0f;
        inter += p * t;
        card  += p + t;
        st    += t;
    }
    float b;
    b = blockReduceSum(inter, red); if (threadIdx.x == 0) atomicAdd(&g_acc[0], (double)b);
    b = blockReduceSum(card,  red); if (threadIdx.x == 0) atomicAdd(&g_acc[1], (double)b);
    b = blockReduceSum(st,    red); if (threadIdx.x == 0) atomicAdd(&g_acc[2], (double)b);
}

// ---------------------------------------------------------------------------
// Fused step: e = erode(im) [cross-min], d = dilate(e) [3x3 max],
// delta = relu(im - d), sk += relu(delta - sk*delta), im_next = e.
// Boundary semantics: erode pads with +inf (min ignores), dilate pads with
// -inf (max ignores) -> e forced to -inf at out-of-image positions.
__global__ __launch_bounds__(STEP_THREADS)
void step_kernel(int src, int write_next) {
    const float* im  = src ? g_buf1 : g_buf0;
    float*       imn = src ? g_buf0 : g_buf1;

    __shared__ float s_im[(TY + 4) * (TX + 4)];
    __shared__ float s_e [(TY + 2) * (TX + 2)];

    const int plane = blockIdx.z;
    const int x0 = blockIdx.x * TX;
    const int y0 = blockIdx.y * TY;
    const int tid = threadIdx.x;

    const float* base = im + (size_t)plane * PLANE_SZ;

    // Phase 1: load im tile with halo 2 (out-of-image -> +inf)
    const float PINF = __int_as_float(0x7f800000);
    const float NINF = __int_as_float(0xff800000);
    #pragma unroll
    for (int idx = tid; idx < (TX + 4) * (TY + 4); idx += STEP_THREADS) {
        int lx = idx % (TX + 4);
        int ly = idx / (TX + 4);
        int gx = x0 + lx - 2;
        int gy = y0 + ly - 2;
        float v = PINF;
        if (gx >= 0 && gx < W && gy >= 0 && gy < H) v = base[gy * W + gx];
        s_im[idx] = v;
    }
    __syncthreads();

    // Phase 2: erode on tile + halo 1 (out-of-image -> -inf for the dilate)
    #pragma unroll
    for (int idx = tid; idx < (TX + 2) * (TY + 2); idx += STEP_THREADS) {
        int lx = idx % (TX + 2);
        int ly = idx / (TX + 2);
        int gx = x0 + lx - 1;
        int gy = y0 + ly - 1;
        float e;
        if (gx < 0 || gx >= W || gy < 0 || gy >= H) {
            e = NINF;
        } else {
            // s_im[(a)*(TX+4)+b] holds global (y0+a-2, x0+b-2); (gy,gx)=(ly+1,lx+1)
            const float* c = &s_im[(ly + 1) * (TX + 4) + (lx + 1)];
            float ce = c[0];
            float up = c[-(TX + 4)];
            float dn = c[ (TX + 4)];
            float lf = c[-1];
            float rt = c[ 1];
            e = fminf(fminf(fminf(up, dn), fminf(lf, rt)), ce);
        }
        s_e[idx] = e;
    }
    __syncthreads();

    // Phase 3: dilate(e), delta, sk update, write e as next im
    float* skb  = g_sk + (size_t)plane * PLANE_SZ;
    float* imnb = imn  + (size_t)plane * PLANE_SZ;
    #pragma unroll
    for (int idx = tid; idx < TX * TY; idx += STEP_THREADS) {
        int lx = idx % TX;
        int ly = idx / TX;
        int gx = x0 + lx;
        int gy = y0 + ly;
        const float* e0 = &s_e[ly * (TX + 2) + lx];  // top-left of 3x3 around (gy,gx)
        float d = e0[0];
        d = fmaxf(d, e0[1]);
        d = fmaxf(d, e0[2]);
        d = fmaxf(d, e0[TX + 2 + 0]);
        d = fmaxf(d, e0[TX + 2 + 1]);
        d = fmaxf(d, e0[TX + 2 + 2]);
        d = fmaxf(d, e0[2 * (TX + 2) + 0]);
        d = fmaxf(d, e0[2 * (TX + 2) + 1]);
        d = fmaxf(d, e0[2 * (TX + 2) + 2]);

        float imv   = s_im[(ly + 2) * (TX + 4) + (lx + 2)];
        float delta = fmaxf(imv - d, 0.0f);

        int g = gy * W + gx;
        float sk = skb[g];
        sk = sk + fmaxf(delta - sk * delta, 0.0f);
        skb[g] = sk;
        if (write_next) imnb[g] = e0[TX + 2 + 1];  // e at center
    }
}

// ---------------------------------------------------------------------------
__global__ void reduce_skel_kernel() {
    __shared__ float red[32];
    int tid = blockIdx.x * blockDim.x + threadIdx.x;
    int stride = gridDim.x * blockDim.x;
    float sot = 0.0f, so = 0.0f, stk = 0.0f;
    for (int i = tid; i < HALF; i += stride) {
        float o = g_sk[i];
        float t = g_sk[HALF + i];
        sot += o * t;
        so  += o;
        stk += t;
    }
    float b;
    b = blockReduceSum(sot, red); if (threadIdx.x == 0) atomicAdd(&g_acc[3], (double)b);
    b = blockReduceSum(so,  red); if (threadIdx.x == 0) atomicAdd(&g_acc[4], (double)b);
    b = blockReduceSum(stk, red); if (threadIdx.x == 0) atomicAdd(&g_acc[5], (double)b);
}

__global__ void finalize_kernel(float* out) {
    double inter = g_acc[0], card = g_acc[1], sumt = g_acc[2];
    double score = (2.0 * inter + 1.0) / fmax(card + 1.0, 1e-7);
    double dice  = (1.0 - score) * (sumt > 0.0 ? 1.0 : 0.0);

    double sot = g_acc[3], so = g_acc[4], stk = g_acc[5];
    double tprec = (sot + 1.0) / (so + 1.0);
    double tsens = (sot + 1.0) / (stk + 1.0);
    double cscore = 2.0 * (tprec * tsens) / (tprec + tsens);
    double cl = (1.0 - cscore) * (stk > 0.0 ? 1.0 : 0.0);

    out[0] = (float)(0.5 * dice + 0.5 * cl);
}

// ---------------------------------------------------------------------------
extern "C" void kernel_launch(void* const* d_in, const int* in_sizes, int n_in,
                              void* d_out, int out_size) {
    (void)in_sizes; (void)n_in; (void)out_size;
    const float* logits = (const float*)d_in[0];
    const int*   target = (const int*)d_in[1];

    zero_acc_kernel<<<1, 32>>>();
    init_kernel<<<2048, 256>>>(logits, target);

    dim3 grid(W / TX, H / TY, NPLANE);
    for (int k = 0; k < N_STEPS; k++) {
        step_kernel<<<grid, STEP_THREADS>>>(k & 1, (k == N_STEPS - 1) ? 0 : 1);
    }

    reduce_skel_kernel<<<2048, 256>>>();
    finalize_kernel<<<1, 1>>>((float*)d_out);
}

// round 2
// speedup vs baseline: 1.7650x; 1.7650x over previous
#include <cuda_runtime.h>
#include <math.h>

#define H 1024
#define W 1024
#define PLANE_SZ (H * W)
#define HALFN (8 * PLANE_SZ)
#define TOTAL (16 * PLANE_SZ)

#define TX 128
#define TY 128
#define HALO 12
#define BW (TX + 2 * HALO)   // 152
#define BH (TY + 2 * HALO)   // 152
#define SMEM_ELEMS (BW * BH) // 23104
#define NT 1024
#define RPT (TY / 8)         // 16 rows per thread in pass 2

#define IDX(ly, lx) (((ly) + HALO) * BW + (lx) + HALO)

// -------- device scratch --------
__device__ float g_sk[TOTAL];
__device__ double g_acc[6];  // [0]=inter [1]=card [2]=sum_t [3]=s_ot [4]=s_o [5]=s_tskel

// ---------------------------------------------------------------------------
__device__ __forceinline__ float blockReduceSum(float v, float* red) {
    #pragma unroll
    for (int o = 16; o > 0; o >>= 1) v += __shfl_down_sync(0xffffffffu, v, o);
    int lane = threadIdx.x & 31;
    int wid  = threadIdx.x >> 5;
    if (lane == 0) red[wid] = v;
    __syncthreads();
    int nwarp = blockDim.x >> 5;
    v = (threadIdx.x < nwarp) ? red[threadIdx.x] : 0.0f;
    if (wid == 0) {
        #pragma unroll
        for (int o = 16; o > 0; o >>= 1) v += __shfl_down_sync(0xffffffffu, v, o);
    }
    __syncthreads();
    return v;
}

__global__ void zero_acc_kernel() {
    if (threadIdx.x < 6) g_acc[threadIdx.x] = 0.0;
}

// ---------------------------------------------------------------------------
__device__ __forceinline__ float dilate_remap(float v) {
    // stored out-of-image marker is +inf; real values are in [0,1].
    return v > 2.0f ? __int_as_float(0xff800000) : v;
}

template<bool BORDER>
__device__ __forceinline__ void skel_tile_impl(const float* __restrict__ logits,
                                               const int* __restrict__ target,
                                               float* __restrict__ A,
                                               float* __restrict__ B,
                                               float* red)
{
    const int plane = blockIdx.z;
    const int x0 = blockIdx.x * TX;
    const int y0 = blockIdx.y * TY;
    const int tid = threadIdx.x;
    const int tx = tid & (TX - 1);
    const int tg = tid >> 7;            // 0..7
    const bool is_prob = plane < 8;
    const int p8 = is_prob ? plane : plane - 8;
    const float PINF = __int_as_float(0x7f800000);

    const float* lg = logits + (size_t)p8 * PLANE_SZ;
    const int*   tp = target + (size_t)p8 * PLANE_SZ;

    // ---- Load E0 tile (+halo 12) with sigmoid/cast fused; dice partial sums
    float s_inter = 0.f, s_card = 0.f;
    for (int idx = tid; idx < SMEM_ELEMS; idx += NT) {
        int ly = idx / BW;
        int lx = idx - ly * BW - HALO;
        ly -= HALO;
        int gx = x0 + lx, gy = y0 + ly;
        float v;
        bool in = true;
        if (BORDER) in = ((unsigned)gx < W) && ((unsigned)gy < H);
        if (in) {
            int g = gy * W + gx;
            if (is_prob) v = 1.0f / (1.0f + __expf(-lg[g]));
            else         v = (float)tp[g];
        } else v = PINF;
        A[idx] = v;
        if (((unsigned)lx < TX) & ((unsigned)ly < TY)) {
            if (is_prob) {
                float t = (float)tp[gy * W + gx];
                s_inter += v * t;
                s_card  += v;
            } else {
                s_card += v;   // sum over target
            }
        }
    }
    // dice atomics (card gets both Σp and Σt contributions)
    {
        float b;
        b = blockReduceSum(s_inter, red);
        if (tid == 0 && is_prob) atomicAdd(&g_acc[0], (double)b);
        b = blockReduceSum(s_card, red);
        if (tid == 0) {
            atomicAdd(&g_acc[1], (double)b);
            if (!is_prob) atomicAdd(&g_acc[2], (double)b);
        }
    }
    __syncthreads();

    float* cur = A;   // E_j
    float* nxt = B;   // E_{j+1}
    float sk[RPT];
    #pragma unroll
    for (int r = 0; r < RPT; r++) sk[r] = 0.0f;

    for (int j = 0; j < 11; j++) {
        const int m = 11 - j;   // margin on which E_{j+1} is computed

        // ---- Pass 1: erode (cross-min) cur -> nxt on margin m, rolling regs
        {
            const int rows  = TY + 2 * m;
            const int chunk = (rows + 7) >> 3;
            int rs = -m + tg * chunk;
            int re = rs + chunk;
            if (re > TY + m) re = TY + m;
            const int lx1 = tx - m;
            const int lx2 = tx + (TX - m);
            const bool has2 = tx < 2 * m;
            if (rs < re) {
                float a1 = cur[IDX(rs - 1, lx1)];
                float b1 = cur[IDX(rs,     lx1)];
                float a2 = 0.f, b2 = 0.f;
                if (has2) { a2 = cur[IDX(rs - 1, lx2)]; b2 = cur[IDX(rs, lx2)]; }
                for (int y = rs; y < re; y++) {
                    {
                        float c1 = cur[IDX(y + 1, lx1)];
                        float l1 = cur[IDX(y, lx1 - 1)];
                        float r1 = cur[IDX(y, lx1 + 1)];
                        float e = fminf(fminf(fminf(a1, b1), c1), fminf(l1, r1));
                        if (BORDER) {
                            int gx = x0 + lx1, gy = y0 + y;
                            if (((unsigned)gx >= W) | ((unsigned)gy >= H)) e = PINF;
                        }
                        nxt[IDX(y, lx1)] = e;
                        a1 = b1; b1 = c1;
                    }
                    if (has2) {
                        float c2 = cur[IDX(y + 1, lx2)];
                        float l2 = cur[IDX(y, lx2 - 1)];
                        float r2 = cur[IDX(y, lx2 + 1)];
                        float e = fminf(fminf(fminf(a2, b2), c2), fminf(l2, r2));
                        if (BORDER) {
                            int gx = x0 + lx2, gy = y0 + y;
                            if (((unsigned)gx >= W) | ((unsigned)gy >= H)) e = PINF;
                        }
                        nxt[IDX(y, lx2)] = e;
                        a2 = b2; b2 = c2;
                    }
                }
            }
            __syncthreads();
        }

        // ---- Pass 2: d = dilate3x3(nxt), delta = relu(cur - d), sk update (center)
        {
            const int x  = tx;
            const int ys = tg * RPT;
            float v0, v1, v2, h0, h1;
            v0 = nxt[IDX(ys - 1, x - 1)]; v1 = nxt[IDX(ys - 1, x)]; v2 = nxt[IDX(ys - 1, x + 1)];
            if (BORDER) { v0 = dilate_remap(v0); v1 = dilate_remap(v1); v2 = dilate_remap(v2); }
            h0 = fmaxf(fmaxf(v0, v1), v2);
            v0 = nxt[IDX(ys, x - 1)]; v1 = nxt[IDX(ys, x)]; v2 = nxt[IDX(ys, x + 1)];
            if (BORDER) { v0 = dilate_remap(v0); v1 = dilate_remap(v1); v2 = dilate_remap(v2); }
            h1 = fmaxf(fmaxf(v0, v1), v2);
            #pragma unroll
            for (int r = 0; r < RPT; r++) {
                int y = ys + r;
                float w0 = nxt[IDX(y + 1, x - 1)];
                float w1 = nxt[IDX(y + 1, x)];
                float w2 = nxt[IDX(y + 1, x + 1)];
                if (BORDER) { w0 = dilate_remap(w0); w1 = dilate_remap(w1); w2 = dilate_remap(w2); }
                float h2 = fmaxf(fmaxf(w0, w1), w2);
                float d  = fmaxf(fmaxf(h0, h1), h2);
                float av = cur[IDX(y, x)];
                float delta = fmaxf(av - d, 0.0f);
                float s = sk[r];
                sk[r] = s + fmaxf(delta - s * delta, 0.0f);
                h0 = h1; h1 = h2;
            }
            __syncthreads();
        }

        float* t = cur; cur = nxt; nxt = t;
    }

    // ---- write final sk (coalesced: consecutive tx -> consecutive gx)
    float* out = g_sk + (size_t)plane * PLANE_SZ + (size_t)(y0 + tg * RPT) * W + (x0 + tx);
    #pragma unroll
    for (int r = 0; r < RPT; r++) out[(size_t)r * W] = sk[r];
}

__global__ void __launch_bounds__(NT, 1)
fused_skel_kernel(const float* __restrict__ logits, const int* __restrict__ target)
{
    extern __shared__ float smem[];
    __shared__ float red[32];
    float* A = smem;
    float* B = smem + SMEM_ELEMS;
    bool border = (blockIdx.x == 0) | (blockIdx.x == gridDim.x - 1) |
                  (blockIdx.y == 0) | (blockIdx.y == gridDim.y - 1);
    if (border) skel_tile_impl<true >(logits, target, A, B, red);
    else        skel_tile_impl<false>(logits, target, A, B, red);
}

// ---------------------------------------------------------------------------
__global__ void reduce_skel_kernel() {
    __shared__ float red[32];
    int tid = blockIdx.x * blockDim.x + threadIdx.x;
    int stride = gridDim.x * blockDim.x;
    float sot = 0.0f, so = 0.0f, stk = 0.0f;
    for (int i = tid; i < HALFN; i += stride) {
        float o = g_sk[i];
        float t = g_sk[HALFN + i];
        sot += o * t;
        so  += o;
        stk += t;
    }
    float b;
    b = blockReduceSum(sot, red); if (threadIdx.x == 0) atomicAdd(&g_acc[3], (double)b);
    b = blockReduceSum(so,  red); if (threadIdx.x == 0) atomicAdd(&g_acc[4], (double)b);
    b = blockReduceSum(stk, red); if (threadIdx.x == 0) atomicAdd(&g_acc[5], (double)b);
}

__global__ void finalize_kernel(float* out) {
    double inter = g_acc[0], card = g_acc[1], sumt = g_acc[2];
    double score = (2.0 * inter + 1.0) / fmax(card + 1.0, 1e-7);
    double dice  = (1.0 - score) * (sumt > 0.0 ? 1.0 : 0.0);

    double sot = g_acc[3], so = g_acc[4], stk = g_acc[5];
    double tprec = (sot + 1.0) / (so + 1.0);
    double tsens = (sot + 1.0) / (stk + 1.0);
    double cscore = 2.0 * (tprec * tsens) / (tprec + tsens);
    double cl = (1.0 - cscore) * (stk > 0.0 ? 1.0 : 0.0);

    out[0] = (float)(0.5 * dice + 0.5 * cl);
}

// ---------------------------------------------------------------------------
extern "C" void kernel_launch(void* const* d_in, const int* in_sizes, int n_in,
                              void* d_out, int out_size) {
    (void)in_sizes; (void)n_in; (void)out_size;
    const float* logits = (const float*)d_in[0];
    const int*   target = (const int*)d_in[1];

    cudaFuncSetAttribute(fused_skel_kernel,
                         cudaFuncAttributeMaxDynamicSharedMemorySize,
                         2 * SMEM_ELEMS * (int)sizeof(float));

    zero_acc_kernel<<<1, 32>>>();
    dim3 grid(W / TX, H / TY, 16);
    fused_skel_kernel<<<grid, NT, 2 * SMEM_ELEMS * sizeof(float)>>>(logits, target);
    reduce_skel_kernel<<<2048, 256>>>();
    finalize_kernel<<<1, 1>>>((float*)d_out);
}

// round 3
// speedup vs baseline: 2.1476x; 1.2168x over previous
#include <cuda_runtime.h>
#include <math.h>

#define H 1024
#define W 1024
#define PLANE_SZ (H * W)
#define HALFN (8 * PLANE_SZ)
#define TOTAL (16 * PLANE_SZ)

#define TX 128
#define TY 128
#define SW 156                 // smem row stride in floats (incl. 2 guard cols each side)
#define SWP 78                 // row stride in float2
#define BH 152
#define SMEM_F2 (SWP * BH)     // 11856 float2 per buffer
#define NT 1024

// -------- device scratch --------
__device__ float g_sk[TOTAL];
__device__ double g_acc[6];  // [0]=inter [1]=card [2]=sum_t [3]=s_ot [4]=s_o [5]=s_tskel

// ---------------------------------------------------------------------------
__device__ __forceinline__ float blockReduceSum(float v, float* red) {
    #pragma unroll
    for (int o = 16; o > 0; o >>= 1) v += __shfl_down_sync(0xffffffffu, v, o);
    int lane = threadIdx.x & 31;
    int wid  = threadIdx.x >> 5;
    if (lane == 0) red[wid] = v;
    __syncthreads();
    int nwarp = blockDim.x >> 5;
    v = (threadIdx.x < nwarp) ? red[threadIdx.x] : 0.0f;
    if (wid == 0) {
        #pragma unroll
        for (int o = 16; o > 0; o >>= 1) v += __shfl_down_sync(0xffffffffu, v, o);
    }
    __syncthreads();
    return v;
}

__global__ void zero_acc_kernel() {
    if (threadIdx.x < 6) g_acc[threadIdx.x] = 0.0;
}

__device__ __forceinline__ float2 remap2(float2 v) {
    const float NINF = __int_as_float(0xff800000);
    // real values are in [0,1]; +inf marks out-of-image -> must lose the max
    v.x = v.x > 2.0f ? NINF : v.x;
    v.y = v.y > 2.0f ? NINF : v.y;
    return v;
}

// ---------------------------------------------------------------------------
template<bool BORDER>
__device__ __forceinline__ void tile_impl(const float* __restrict__ logits,
                                          const int* __restrict__ target,
                                          float2* __restrict__ A,
                                          float2* __restrict__ B,
                                          float* red)
{
    const int plane = blockIdx.z;
    const int x0 = blockIdx.x * TX;
    const int y0 = blockIdx.y * TY;
    const int tid = threadIdx.x;
    const bool is_prob = plane < 8;
    const int p8 = is_prob ? plane : plane - 8;
    const float PINF = __int_as_float(0x7f800000);

    const float* lg = logits + (size_t)p8 * PLANE_SZ;
    const int*   tp = target + (size_t)p8 * PLANE_SZ;

    // ---- Load E0 (+guards) as float2; fuse sigmoid/cast + dice partial sums
    float s_inter = 0.f, s_card = 0.f;
    for (int idx = tid; idx < SMEM_F2; idx += NT) {
        int r  = idx / SWP;
        int cp = idx - r * SWP;
        int gx = x0 - 14 + 2 * cp;       // even; both components share in/out status
        int gy = y0 - 12 + r;
        float2 v;
        bool guard = (cp == 0) | (cp == SWP - 1);
        bool in = !guard && (!BORDER || (((unsigned)gx < W) & ((unsigned)gy < H)));
        if (in) {
            size_t g = (size_t)gy * W + gx;
            if (is_prob) {
                float2 l = *(const float2*)(lg + g);
                v.x = 1.0f / (1.0f + __expf(-l.x));
                v.y = 1.0f / (1.0f + __expf(-l.y));
            } else {
                int2 t = *(const int2*)(tp + g);
                v.x = (float)t.x;
                v.y = (float)t.y;
            }
        } else {
            v.x = PINF; v.y = PINF;
        }
        A[idx] = v;
        // dice sums over the center 128x128 (always in-image)
        if ((r >= 12) & (r < 140) & (cp >= 7) & (cp < 71)) {
            if (is_prob) {
                int2 t = *(const int2*)(tp + (size_t)gy * W + gx);
                s_inter += v.x * (float)t.x + v.y * (float)t.y;
                s_card  += v.x + v.y;
            } else {
                s_card += v.x + v.y;
            }
        }
    }
    {
        float b;
        b = blockReduceSum(s_inter, red);
        if (tid == 0 && is_prob) atomicAdd(&g_acc[0], (double)b);
        b = blockReduceSum(s_card, red);
        if (tid == 0) {
            atomicAdd(&g_acc[1], (double)b);
            if (!is_prob) atomicAdd(&g_acc[2], (double)b);
        }
    }
    __syncthreads();

    float2* cur = A;
    float2* nxt = B;

    // pass-1 mapping: 988 active threads = 76 pairs x 13 row-groups
    const int  p1   = tid % 76;
    const int  g1   = tid / 76;
    const bool act1 = tid < 988;
    const int  rs   = 1 + g1 * 12;
    const int  re   = (rs + 12 < 151) ? rs + 12 : 151;
    const bool xo   = BORDER && ((unsigned)(x0 - 12 + 2 * p1) >= W);

    // pass-2 mapping: 64 pairs x 16 row-groups x 8 rows
    const int q2 = tid & 63;
    const int g2 = tid >> 6;
    const int y2 = 12 + g2 * 8;              // first output buffer row
    const int cx = x0 + 2 * q2;              // first output image col
    const bool edge2 = BORDER && ((cx == 0) | (cx >= W - 2) |
                                  (y0 + g2 * 8 == 0) | (y0 + g2 * 8 + 7 == H - 1));

    float2 sk[8];
    #pragma unroll
    for (int i = 0; i < 8; i++) { sk[i].x = 0.f; sk[i].y = 0.f; }

    for (int j = 0; j < 11; j++) {
        // ---- Pass 1: erode (cross-min) cur -> nxt on fixed margin-11 region
        if (act1) {
            float2 a = cur[(rs - 1) * SWP + p1 + 1];
            float2 b = cur[ rs      * SWP + p1 + 1];
            for (int r = rs; r < re; r++) {
                float2 c  = cur[(r + 1) * SWP + p1 + 1];
                float2 Lv = cur[r * SWP + p1];
                float2 Rv = cur[r * SWP + p1 + 2];
                float2 e;
                e.x = fminf(fminf(a.x, c.x), fminf(fminf(Lv.y, b.y), b.x));
                e.y = fminf(fminf(a.y, c.y), fminf(fminf(b.x, Rv.x), b.y));
                if (BORDER) {
                    bool yo = (unsigned)(y0 - 12 + r) >= H;
                    if (xo | yo) { e.x = PINF; e.y = PINF; }
                }
                nxt[r * SWP + p1 + 1] = e;
                a = b; b = c;
            }
        }
        __syncthreads();

        // ---- Pass 2: d = dilate3x3(nxt), delta = relu(cur - d), sk update
        {
            float2 h0, h1;
            {
                float2 Lv = nxt[(y2 - 1) * SWP + 6 + q2];
                float2 Cv = nxt[(y2 - 1) * SWP + 7 + q2];
                float2 Rv = nxt[(y2 - 1) * SWP + 8 + q2];
                if (BORDER && edge2) { Lv = remap2(Lv); Cv = remap2(Cv); Rv = remap2(Rv); }
                float m = fmaxf(Cv.x, Cv.y);
                h0.x = fmaxf(m, Lv.y); h0.y = fmaxf(m, Rv.x);
            }
            {
                float2 Lv = nxt[y2 * SWP + 6 + q2];
                float2 Cv = nxt[y2 * SWP + 7 + q2];
                float2 Rv = nxt[y2 * SWP + 8 + q2];
                if (BORDER && edge2) { Lv = remap2(Lv); Cv = remap2(Cv); Rv = remap2(Rv); }
                float m = fmaxf(Cv.x, Cv.y);
                h1.x = fmaxf(m, Lv.y); h1.y = fmaxf(m, Rv.x);
            }
            #pragma unroll
            for (int i = 0; i < 8; i++) {
                int r = y2 + i;
                float2 h2;
                {
                    float2 Lv = nxt[(r + 1) * SWP + 6 + q2];
                    float2 Cv = nxt[(r + 1) * SWP + 7 + q2];
                    float2 Rv = nxt[(r + 1) * SWP + 8 + q2];
                    if (BORDER && edge2) { Lv = remap2(Lv); Cv = remap2(Cv); Rv = remap2(Rv); }
                    float m = fmaxf(Cv.x, Cv.y);
                    h2.x = fmaxf(m, Lv.y); h2.y = fmaxf(m, Rv.x);
                }
                float dx = fmaxf(fmaxf(h0.x, h1.x), h2.x);
                float dy = fmaxf(fmaxf(h0.y, h1.y), h2.y);
                float2 av = cur[r * SWP + 7 + q2];
                float ex = fmaxf(av.x - dx, 0.0f);
                float ey = fmaxf(av.y - dy, 0.0f);
                sk[i].x += fmaxf(ex - sk[i].x * ex, 0.0f);
                sk[i].y += fmaxf(ey - sk[i].y * ey, 0.0f);
                h0 = h1; h1 = h2;
            }
        }
        __syncthreads();

        float2* t = cur; cur = nxt; nxt = t;
    }

    // ---- write sk (coalesced float2 stores)
    float2* out = (float2*)(g_sk + (size_t)plane * PLANE_SZ +
                            (size_t)(y0 + g2 * 8) * W + cx);
    #pragma unroll
    for (int i = 0; i < 8; i++) out[(size_t)i * (W / 2)] = sk[i];
}

__global__ void __launch_bounds__(NT, 1)
fused_skel_kernel(const float* __restrict__ logits, const int* __restrict__ target)
{
    extern __shared__ float2 smem[];
    __shared__ float red[32];
    float2* A = smem;
    float2* B = smem + SMEM_F2;
    bool border = (blockIdx.x == 0) | (blockIdx.x == gridDim.x - 1) |
                  (blockIdx.y == 0) | (blockIdx.y == gridDim.y - 1);
    if (border) tile_impl<true >(logits, target, A, B, red);
    else        tile_impl<false>(logits, target, A, B, red);
}

// ---------------------------------------------------------------------------
__global__ void reduce_skel_kernel() {
    __shared__ float red[32];
    int tid = blockIdx.x * blockDim.x + threadIdx.x;
    int stride = gridDim.x * blockDim.x;
    const float4* o4 = (const float4*)g_sk;
    const float4* t4 = (const float4*)(g_sk + HALFN);
    float sot = 0.0f, so = 0.0f, stk = 0.0f;
    for (int i = tid; i < HALFN / 4; i += stride) {
        float4 o = o4[i];
        float4 t = t4[i];
        sot += o.x * t.x + o.y * t.y + o.z * t.z + o.w * t.w;
        so  += o.x + o.y + o.z + o.w;
        stk += t.x + t.y + t.z + t.w;
    }
    float b;
    b = blockReduceSum(sot, red); if (threadIdx.x == 0) atomicAdd(&g_acc[3], (double)b);
    b = blockReduceSum(so,  red); if (threadIdx.x == 0) atomicAdd(&g_acc[4], (double)b);
    b = blockReduceSum(stk, red); if (threadIdx.x == 0) atomicAdd(&g_acc[5], (double)b);
}

__global__ void finalize_kernel(float* out) {
    double inter = g_acc[0], card = g_acc[1], sumt = g_acc[2];
    double score = (2.0 * inter + 1.0) / fmax(card + 1.0, 1e-7);
    double dice  = (1.0 - score) * (sumt > 0.0 ? 1.0 : 0.0);

    double sot = g_acc[3], so = g_acc[4], stk = g_acc[5];
    double tprec = (sot + 1.0) / (so + 1.0);
    double tsens = (sot + 1.0) / (stk + 1.0);
    double cscore = 2.0 * (tprec * tsens) / (tprec + tsens);
    double cl = (1.0 - cscore) * (stk > 0.0 ? 1.0 : 0.0);

    out[0] = (float)(0.5 * dice + 0.5 * cl);
}

// ---------------------------------------------------------------------------
extern "C" void kernel_launch(void* const* d_in, const int* in_sizes, int n_in,
                              void* d_out, int out_size) {
    (void)in_sizes; (void)n_in; (void)out_size;
    const float* logits = (const float*)d_in[0];
    const int*   target = (const int*)d_in[1];

    cudaFuncSetAttribute(fused_skel_kernel,
                         cudaFuncAttributeMaxDynamicSharedMemorySize,
                         2 * SMEM_F2 * (int)sizeof(float2));

    zero_acc_kernel<<<1, 32>>>();
    dim3 grid(W / TX, H / TY, 16);
    fused_skel_kernel<<<grid, NT, 2 * SMEM_F2 * sizeof(float2)>>>(logits, target);
    reduce_skel_kernel<<<2048, 256>>>();
    finalize_kernel<<<1, 1>>>((float*)d_out);
}

// round 4
// speedup vs baseline: 2.9836x; 1.3893x over previous
#include <cuda_runtime.h>
#include <cuda_fp16.h>
#include <math.h>

#define H 1024
#define W 1024
#define PLANE_SZ (H * W)

#define NT 1024
#define SWH 80            // half2 words per smem row (152px=76 half2 + 2 guard half2 each side)
#define ROWSB 152
#define BUFW (ROWSB * SWH) // 12160 uint32 = 48.64 KB per buffer
#define PINF2 0x7C007C00u

__device__ double g_acc[6];  // [0]=inter [1]=card [2]=sum_t [3]=s_ot [4]=s_o [5]=s_tskel

// ---------------------------------------------------------------------------
__device__ __forceinline__ unsigned hmin2u(unsigned a, unsigned b) {
    __half2 r = __hmin2(*(__half2*)&a, *(__half2*)&b);
    return *(unsigned*)&r;
}
__device__ __forceinline__ unsigned hmax2u(unsigned a, unsigned b) {
    __half2 r = __hmax2(*(__half2*)&a, *(__half2*)&b);
    return *(unsigned*)&r;
}
__device__ __forceinline__ unsigned hsub2u(unsigned a, unsigned b) {
    __half2 r = __hsub2(*(__half2*)&a, *(__half2*)&b);
    return *(unsigned*)&r;
}
__device__ __forceinline__ unsigned pack2(float a, float b) {
    __half2 h = __floats2half2_rn(a, b);  // .x=a(low)=even px, .y=b(high)=odd px
    return *(unsigned*)&h;
}
__device__ __forceinline__ float2 unpack2(unsigned v) {
    return __half22float2(*(__half2*)&v);
}
// +inf marker (out-of-image for erode) -> -inf (neutral for dilate)
__device__ __forceinline__ unsigned remap2u(unsigned v) {
    unsigned m = __vcmpeq2(v, PINF2) & 0x80008000u;
    return v | m;
}

__device__ __forceinline__ float blockReduceSum(float v, float* red) {
    #pragma unroll
    for (int o = 16; o > 0; o >>= 1) v += __shfl_down_sync(0xffffffffu, v, o);
    int lane = threadIdx.x & 31;
    int wid  = threadIdx.x >> 5;
    if (lane == 0) red[wid] = v;
    __syncthreads();
    v = (threadIdx.x < 32) ? red[threadIdx.x] : 0.0f;
    if (wid == 0) {
        #pragma unroll
        for (int o = 16; o > 0; o >>= 1) v += __shfl_down_sync(0xffffffffu, v, o);
    }
    __syncthreads();
    return v;
}

__global__ void zero_acc_kernel() {
    if (threadIdx.x < 6) g_acc[threadIdx.x] = 0.0;
}

// ---------------------------------------------------------------------------
// One morphology chain (11 fused erode+dilate+skel steps) on one plane.
// sk[16] = fp32 skeleton for this thread's 4 rows x 4 px output patch.
template<bool BORDER, bool ISPROB>
__device__ __forceinline__ void run_chain(const float* __restrict__ lg,
                                          const int* __restrict__ tp,
                                          unsigned* __restrict__ A,
                                          unsigned* __restrict__ B,
                                          float* red,
                                          float* sk,
                                          int x0, int y0)
{
    const int tid = threadIdx.x;

    // ---- init load: sigmoid/cast -> half2 tiles, fused dice partial sums
    float s_inter = 0.f, s_card = 0.f;
    for (int idx = tid; idx < ROWSB * 40; idx += NT) {
        int r = idx / 40;
        int u = idx - r * 40;            // uint2 (4px) column, 0..39
        int px = x0 + 4 * u - 16;
        int gy = y0 - 12 + r;
        bool in = (u != 0) & (u != 39);
        if (BORDER) in = in && ((unsigned)px < W) && ((unsigned)gy < H);
        uint2 val;
        if (in) {
            size_t g = (size_t)gy * W + px;
            bool center = (r >= 12) & (r < 140) & (u >= 4) & (u < 36);
            if (ISPROB) {
                float4 l = *(const float4*)(lg + g);
                float p0 = 1.0f / (1.0f + __expf(-l.x));
                float p1 = 1.0f / (1.0f + __expf(-l.y));
                float p2 = 1.0f / (1.0f + __expf(-l.z));
                float p3 = 1.0f / (1.0f + __expf(-l.w));
                val.x = pack2(p0, p1);
                val.y = pack2(p2, p3);
                if (center) {
                    int4 t = *(const int4*)(tp + g);
                    s_inter += p0 * (float)t.x + p1 * (float)t.y +
                               p2 * (float)t.z + p3 * (float)t.w;
                    s_card  += p0 + p1 + p2 + p3;
                }
            } else {
                int4 t = *(const int4*)(tp + g);
                val.x = pack2((float)t.x, (float)t.y);
                val.y = pack2((float)t.z, (float)t.w);
                if (center) s_card += (float)(t.x + t.y + t.z + t.w);
            }
        } else {
            val.x = PINF2; val.y = PINF2;
        }
        *(uint2*)(&A[r * SWH + 2 * u]) = val;
    }
    {
        float b;
        if (ISPROB) {
            b = blockReduceSum(s_inter, red);
            if (tid == 0) atomicAdd(&g_acc[0], (double)b);
        }
        b = blockReduceSum(s_card, red);
        if (tid == 0) {
            atomicAdd(&g_acc[1], (double)b);
            if (!ISPROB) atomicAdd(&g_acc[2], (double)b);
        }
    }
    __syncthreads();

    // pass-1 mapping: 38 uint2 cols x 26 row-groups (988 active threads)
    const int p1c = tid % 38;
    const int g1  = tid / 38;
    const int u1  = 1 + p1c;
    const int rs  = 1 + 6 * g1;
    const int re  = (rs + 6 < 151) ? rs + 6 : 151;  // rows [rs, re)
    const bool act1 = g1 < 26;
    const bool xo0 = BORDER && ((unsigned)(x0 + 4 * u1 - 16) >= W);
    const bool xo1 = BORDER && ((unsigned)(x0 + 4 * u1 - 14) >= W);

    // pass-2 mapping: 32 uint2 cols x 32 groups x 4 rows
    const int c2 = tid & 31;
    const int u2 = 4 + c2;
    const int g2 = tid >> 5;
    const int yb = 12 + 4 * g2;

    #pragma unroll
    for (int i = 0; i < 16; i++) sk[i] = 0.0f;

    unsigned* cur = A;
    unsigned* nxt = B;

    for (int j = 0; j < 11; j++) {
        // ---- Pass 1: erode (cross-min), fixed region rows 1..150, all data cols
        if (act1) {
            uint2 t0 = *(uint2*)(&cur[(rs - 1) * SWH + 2 * u1]);
            uint2 t1 = *(uint2*)(&cur[rs * SWH + 2 * u1]);
            unsigned a0 = t0.x, a1 = t0.y, b0 = t1.x, b1 = t1.y;
            for (int r = rs; r < re; r++) {
                uint2 cc = *(uint2*)(&cur[(r + 1) * SWH + 2 * u1]);
                unsigned Lh = cur[r * SWH + 2 * u1 - 1];
                unsigned Rh = cur[r * SWH + 2 * u1 + 2];
                unsigned Ls0 = __byte_perm(Lh, b0, 0x5432);
                unsigned Rs0 = __byte_perm(b0, b1, 0x5432);
                unsigned Rs1 = __byte_perm(b1, Rh, 0x5432);
                unsigned e0 = hmin2u(hmin2u(a0, cc.x), hmin2u(b0, hmin2u(Ls0, Rs0)));
                unsigned e1 = hmin2u(hmin2u(a1, cc.y), hmin2u(b1, hmin2u(Rs0, Rs1)));
                if (BORDER) {
                    bool yo = (unsigned)(y0 - 12 + r) >= H;
                    if (xo0 | yo) e0 = PINF2;
                    if (xo1 | yo) e1 = PINF2;
                }
                uint2 ee; ee.x = e0; ee.y = e1;
                *(uint2*)(&nxt[r * SWH + 2 * u1]) = ee;
                a0 = b0; a1 = b1; b0 = cc.x; b1 = cc.y;
            }
        }
        __syncthreads();

        // ---- Pass 2: d = dilate3x3(nxt), delta = relu(cur - d), sk update
        {
            unsigned h0a, h0b, h1a, h1b;
            #pragma unroll
            for (int pre = 0; pre < 2; pre++) {
                int r = yb - 1 + pre;
                uint2 C = *(uint2*)(&nxt[r * SWH + 2 * u2]);
                unsigned Lh = nxt[r * SWH + 2 * u2 - 1];
                unsigned Rh = nxt[r * SWH + 2 * u2 + 2];
                if (BORDER) { C.x = remap2u(C.x); C.y = remap2u(C.y);
                              Lh = remap2u(Lh);   Rh = remap2u(Rh); }
                unsigned Ls0 = __byte_perm(Lh, C.x, 0x5432);
                unsigned Rs0 = __byte_perm(C.x, C.y, 0x5432);
                unsigned Rs1 = __byte_perm(C.y, Rh, 0x5432);
                unsigned ha = hmax2u(C.x, hmax2u(Ls0, Rs0));
                unsigned hb = hmax2u(C.y, hmax2u(Rs0, Rs1));
                if (pre == 0) { h0a = ha; h0b = hb; } else { h1a = ha; h1b = hb; }
            }
            #pragma unroll
            for (int i = 0; i < 4; i++) {
                int r = yb + 1 + i;
                uint2 C = *(uint2*)(&nxt[r * SWH + 2 * u2]);
                unsigned Lh = nxt[r * SWH + 2 * u2 - 1];
                unsigned Rh = nxt[r * SWH + 2 * u2 + 2];
                if (BORDER) { C.x = remap2u(C.x); C.y = remap2u(C.y);
                              Lh = remap2u(Lh);   Rh = remap2u(Rh); }
                unsigned Ls0 = __byte_perm(Lh, C.x, 0x5432);
                unsigned Rs0 = __byte_perm(C.x, C.y, 0x5432);
                unsigned Rs1 = __byte_perm(C.y, Rh, 0x5432);
                unsigned h2a = hmax2u(C.x, hmax2u(Ls0, Rs0));
                unsigned h2b = hmax2u(C.y, hmax2u(Rs0, Rs1));
                unsigned d0 = hmax2u(h0a, hmax2u(h1a, h2a));
                unsigned d1 = hmax2u(h0b, hmax2u(h1b, h2b));
                uint2 av = *(uint2*)(&cur[(yb + i) * SWH + 2 * u2]);
                unsigned del0 = hmax2u(hsub2u(av.x, d0), 0u);
                unsigned del1 = hmax2u(hsub2u(av.y, d1), 0u);
                float2 f0 = unpack2(del0);
                float2 f1 = unpack2(del1);
                float s;
                s = sk[4*i+0]; sk[4*i+0] = s + fmaxf(fmaf(-s, f0.x, f0.x), 0.0f);
                s = sk[4*i+1]; sk[4*i+1] = s + fmaxf(fmaf(-s, f0.y, f0.y), 0.0f);
                s = sk[4*i+2]; sk[4*i+2] = s + fmaxf(fmaf(-s, f1.x, f1.x), 0.0f);
                s = sk[4*i+3]; sk[4*i+3] = s + fmaxf(fmaf(-s, f1.y, f1.y), 0.0f);
                h0a = h1a; h0b = h1b; h1a = h2a; h1b = h2b;
            }
        }
        __syncthreads();

        unsigned* t = cur; cur = nxt; nxt = t;
    }
}

// ---------------------------------------------------------------------------
template<bool BORDER>
__device__ __forceinline__ void tile_both(const float* __restrict__ logits,
                                          const int* __restrict__ target,
                                          unsigned* A, unsigned* B, float* red)
{
    const int p8 = blockIdx.z;
    const int x0 = blockIdx.x * 128;
    const int y0 = blockIdx.y * 128;
    const float* lg = logits + (size_t)p8 * PLANE_SZ;
    const int*   tp = target + (size_t)p8 * PLANE_SZ;

    float sk_o[16], sk_t[16];
    run_chain<BORDER, true >(lg, tp, A, B, red, sk_o, x0, y0);
    __syncthreads();
    run_chain<BORDER, false>(lg, tp, A, B, red, sk_t, x0, y0);

    float sot = 0.f, so = 0.f, st = 0.f;
    #pragma unroll
    for (int i = 0; i < 16; i++) {
        sot += sk_o[i] * sk_t[i];
        so  += sk_o[i];
        st  += sk_t[i];
    }
    float b;
    b = blockReduceSum(sot, red); if (threadIdx.x == 0) atomicAdd(&g_acc[3], (double)b);
    b = blockReduceSum(so,  red); if (threadIdx.x == 0) atomicAdd(&g_acc[4], (double)b);
    b = blockReduceSum(st,  red); if (threadIdx.x == 0) atomicAdd(&g_acc[5], (double)b);
}

__global__ void __launch_bounds__(NT, 1)
fused_skel_kernel(const float* __restrict__ logits, const int* __restrict__ target)
{
    extern __shared__ unsigned smem[];
    __shared__ float red[32];
    unsigned* A = smem;
    unsigned* B = smem + BUFW;
    bool border = (blockIdx.x == 0) | (blockIdx.x == gridDim.x - 1) |
                  (blockIdx.y == 0) | (blockIdx.y == gridDim.y - 1);
    if (border) tile_both<true >(logits, target, A, B, red);
    else        tile_both<false>(logits, target, A, B, red);
}

// ---------------------------------------------------------------------------
__global__ void finalize_kernel(float* out) {
    double inter = g_acc[0], card = g_acc[1], sumt = g_acc[2];
    double score = (2.0 * inter + 1.0) / fmax(card + 1.0, 1e-7);
    double dice  = (1.0 - score) * (sumt > 0.0 ? 1.0 : 0.0);

    double sot = g_acc[3], so = g_acc[4], stk = g_acc[5];
    double tprec = (sot + 1.0) / (so + 1.0);
    double tsens = (sot + 1.0) / (stk + 1.0);
    double cscore = 2.0 * (tprec * tsens) / (tprec + tsens);
    double cl = (1.0 - cscore) * (stk > 0.0 ? 1.0 : 0.0);

    out[0] = (float)(0.5 * dice + 0.5 * cl);
}

// ---------------------------------------------------------------------------
extern "C" void kernel_launch(void* const* d_in, const int* in_sizes, int n_in,
                              void* d_out, int out_size) {
    (void)in_sizes; (void)n_in; (void)out_size;
    const float* logits = (const float*)d_in[0];
    const int*   target = (const int*)d_in[1];

    cudaFuncSetAttribute(fused_skel_kernel,
                         cudaFuncAttributeMaxDynamicSharedMemorySize,
                         2 * BUFW * (int)sizeof(unsigned));

    zero_acc_kernel<<<1, 32>>>();
    dim3 grid(W / 128, H / 128, 8);
    fused_skel_kernel<<<grid, NT, 2 * BUFW * sizeof(unsigned)>>>(logits, target);
    finalize_kernel<<<1, 1>>>((float*)d_out);
}

// round 5
// speedup vs baseline: 3.0779x; 1.0316x over previous
#include <cuda_runtime.h>
#include <cuda_fp16.h>

#define H 1024
#define W 1024
#define PLANE_SZ (H * W)

#define NT 1024
#define ROWS 152               // 128 + 2*12 halo rows
#define RW 22                  // uint4 per row: 20 data (160 px, x-halo 16) + 2 guards
#define BUF_U4 (ROWS * RW)     // 3344 uint4 = 53504 B per buffer
#define PINF2 0x7C007C00u
#define NBLOCKS 512

__device__ double g_acc[6];    // [0]=inter [1]=card [2]=sum_t [3]=s_ot [4]=s_o [5]=s_tskel
__device__ unsigned g_done;

// ---------------------------------------------------------------------------
__device__ __forceinline__ unsigned hmin2u(unsigned a, unsigned b) {
    __half2 r = __hmin2(*(__half2*)&a, *(__half2*)&b);
    return *(unsigned*)&r;
}
__device__ __forceinline__ unsigned hmax2u(unsigned a, unsigned b) {
    __half2 r = __hmax2(*(__half2*)&a, *(__half2*)&b);
    return *(unsigned*)&r;
}
__device__ __forceinline__ unsigned hsub2u(unsigned a, unsigned b) {
    __half2 r = __hsub2(*(__half2*)&a, *(__half2*)&b);
    return *(unsigned*)&r;
}
__device__ __forceinline__ unsigned pack2(float a, float b) {
    __half2 h = __floats2half2_rn(a, b);
    return *(unsigned*)&h;
}
__device__ __forceinline__ float2 unpack2(unsigned v) {
    return __half22float2(*(__half2*)&v);
}
// +inf marker (out-of-image, erode-neutral) -> -inf (dilate-neutral)
__device__ __forceinline__ unsigned remap2u(unsigned v) {
    unsigned m = __vcmpeq2(v, PINF2) & 0x80008000u;
    return v | m;
}

__device__ __forceinline__ float blockReduceSum(float v, float* red) {
    #pragma unroll
    for (int o = 16; o > 0; o >>= 1) v += __shfl_down_sync(0xffffffffu, v, o);
    int lane = threadIdx.x & 31;
    int wid  = threadIdx.x >> 5;
    if (lane == 0) red[wid] = v;
    __syncthreads();
    v = (threadIdx.x < 32) ? red[threadIdx.x] : 0.0f;
    if (wid == 0) {
        #pragma unroll
        for (int o = 16; o > 0; o >>= 1) v += __shfl_down_sync(0xffffffffu, v, o);
    }
    __syncthreads();
    return v;
}

// ---------------------------------------------------------------------------
// Erode (5-pt cross min) rows [start,end) of one uint4 column, cur -> nxt.
template<bool BORDER>
__device__ __forceinline__ void erode_pass(const uint4* __restrict__ cur,
                                           uint4* __restrict__ nxt,
                                           int u1, int start, int end,
                                           bool xo0, bool xo1, bool xo2, bool xo3,
                                           int y0)
{
    const unsigned* cur32 = (const unsigned*)cur;
    int base = start * RW + u1;
    uint4 a = cur[base - RW];
    uint4 b = cur[base];
    for (int r = start; r < end; r++) {
        uint4 c = cur[base + RW];
        unsigned Lh = cur32[4 * base - 1];
        unsigned Rh = cur32[4 * base + 4];
        unsigned P0 = __byte_perm(Lh,  b.x, 0x5432);
        unsigned P1 = __byte_perm(b.x, b.y, 0x5432);
        unsigned P2 = __byte_perm(b.y, b.z, 0x5432);
        unsigned P3 = __byte_perm(b.z, b.w, 0x5432);
        unsigned P4 = __byte_perm(b.w, Rh, 0x5432);
        uint4 e;
        e.x = hmin2u(hmin2u(a.x, c.x), hmin2u(b.x, hmin2u(P0, P1)));
        e.y = hmin2u(hmin2u(a.y, c.y), hmin2u(b.y, hmin2u(P1, P2)));
        e.z = hmin2u(hmin2u(a.z, c.z), hmin2u(b.z, hmin2u(P2, P3)));
        e.w = hmin2u(hmin2u(a.w, c.w), hmin2u(b.w, hmin2u(P3, P4)));
        if (BORDER) {
            bool yo = ((unsigned)(y0 - 12 + r) >= H);
            if (xo0 | yo) e.x = PINF2;
            if (xo1 | yo) e.y = PINF2;
            if (xo2 | yo) e.z = PINF2;
            if (xo3 | yo) e.w = PINF2;
        }
        nxt[base] = e;
        a = b; b = c; base += RW;
    }
}

// Horizontal 3-max of one buffer row word (with border remap).
template<bool BORDER>
__device__ __forceinline__ uint4 rowmax_fn(const uint4* __restrict__ nxt,
                                           const unsigned* __restrict__ nxt32,
                                           int base)
{
    uint4 C = nxt[base];
    unsigned Lh = nxt32[4 * base - 1];
    unsigned Rh = nxt32[4 * base + 4];
    if (BORDER) {
        C.x = remap2u(C.x); C.y = remap2u(C.y); C.z = remap2u(C.z); C.w = remap2u(C.w);
        Lh = remap2u(Lh); Rh = remap2u(Rh);
    }
    unsigned P0 = __byte_perm(Lh,  C.x, 0x5432);
    unsigned P1 = __byte_perm(C.x, C.y, 0x5432);
    unsigned P2 = __byte_perm(C.y, C.z, 0x5432);
    unsigned P3 = __byte_perm(C.z, C.w, 0x5432);
    unsigned P4 = __byte_perm(C.w, Rh, 0x5432);
    uint4 h;
    h.x = hmax2u(C.x, hmax2u(P0, P1));
    h.y = hmax2u(C.y, hmax2u(P1, P2));
    h.z = hmax2u(C.z, hmax2u(P2, P3));
    h.w = hmax2u(C.w, hmax2u(P3, P4));
    return h;
}

// Dilate 3x3 of nxt, delta = relu(cur - d), sk update; 2 rows x 8 px.
template<bool BORDER>
__device__ __forceinline__ void dilate_skel(const uint4* __restrict__ cur,
                                            const uint4* __restrict__ nxt,
                                            int u2, int yb, float* sk)
{
    const unsigned* nxt32 = (const unsigned*)nxt;
    uint4 h0 = rowmax_fn<BORDER>(nxt, nxt32, (yb - 1) * RW + u2);
    uint4 h1 = rowmax_fn<BORDER>(nxt, nxt32,  yb      * RW + u2);
    #pragma unroll
    for (int i = 0; i < 2; i++) {
        uint4 h2 = rowmax_fn<BORDER>(nxt, nxt32, (yb + 1 + i) * RW + u2);
        uint4 av = cur[(yb + i) * RW + u2];
        unsigned dw, del; float2 f; float s;

        dw = hmax2u(h0.x, hmax2u(h1.x, h2.x));
        del = hmax2u(hsub2u(av.x, dw), 0u); f = unpack2(del);
        s = sk[i*8+0]; sk[i*8+0] = s + fmaxf(fmaf(-s, f.x, f.x), 0.f);
        s = sk[i*8+1]; sk[i*8+1] = s + fmaxf(fmaf(-s, f.y, f.y), 0.f);

        dw = hmax2u(h0.y, hmax2u(h1.y, h2.y));
        del = hmax2u(hsub2u(av.y, dw), 0u); f = unpack2(del);
        s = sk[i*8+2]; sk[i*8+2] = s + fmaxf(fmaf(-s, f.x, f.x), 0.f);
        s = sk[i*8+3]; sk[i*8+3] = s + fmaxf(fmaf(-s, f.y, f.y), 0.f);

        dw = hmax2u(h0.z, hmax2u(h1.z, h2.z));
        del = hmax2u(hsub2u(av.z, dw), 0u); f = unpack2(del);
        s = sk[i*8+4]; sk[i*8+4] = s + fmaxf(fmaf(-s, f.x, f.x), 0.f);
        s = sk[i*8+5]; sk[i*8+5] = s + fmaxf(fmaf(-s, f.y, f.y), 0.f);

        dw = hmax2u(h0.w, hmax2u(h1.w, h2.w));
        del = hmax2u(hsub2u(av.w, dw), 0u); f = unpack2(del);
        s = sk[i*8+6]; sk[i*8+6] = s + fmaxf(fmaf(-s, f.x, f.x), 0.f);
        s = sk[i*8+7]; sk[i*8+7] = s + fmaxf(fmaf(-s, f.y, f.y), 0.f);

        h0 = h1; h1 = h2;
    }
}

// ---------------------------------------------------------------------------
template<bool BORDER>
__device__ __forceinline__ void tile_run(const float* __restrict__ logits,
                                         const int* __restrict__ target,
                                         uint4* A, uint4* B, uint4* Cb, uint4* Db,
                                         float* red)
{
    const int p8 = blockIdx.z;
    const int x0 = blockIdx.x * 128;
    const int y0 = blockIdx.y * 128;
    const int tid = threadIdx.x;
    const float* lg = logits + (size_t)p8 * PLANE_SZ;
    const int*   tp = target + (size_t)p8 * PLANE_SZ;

    // ---- single load phase: prob -> A, target -> Cb, guards in all buffers,
    //      dice partial sums fused
    float s_inter = 0.f, s_cp = 0.f, s_ct = 0.f;
    for (int idx = tid; idx < BUF_U4; idx += NT) {
        int r = idx / RW;
        int u = idx - r * RW;
        uint4 vp, vt;
        bool guard = (u == 0) | (u == RW - 1);
        if (!guard) {
            int gy = y0 - 12 + r;
            int gxb = x0 - 16 + 8 * (u - 1);
            bool rin = !BORDER || ((unsigned)gy < H);
            size_t rowoff = (size_t)gy * W;
            bool center = (u >= 3) & (u < 19) & (r >= 12) & (r < 140);
            // half 0 (px gxb..gxb+3)
            if (rin && (!BORDER || ((unsigned)gxb < W))) {
                float4 l = *(const float4*)(lg + rowoff + gxb);
                int4   t = *(const int4*)(tp + rowoff + gxb);
                float p0 = 1.0f / (1.0f + __expf(-l.x));
                float p1 = 1.0f / (1.0f + __expf(-l.y));
                float p2 = 1.0f / (1.0f + __expf(-l.z));
                float p3 = 1.0f / (1.0f + __expf(-l.w));
                vp.x = pack2(p0, p1); vp.y = pack2(p2, p3);
                vt.x = pack2((float)t.x, (float)t.y);
                vt.y = pack2((float)t.z, (float)t.w);
                if (center) {
                    s_inter += p0*(float)t.x + p1*(float)t.y + p2*(float)t.z + p3*(float)t.w;
                    s_cp += p0 + p1 + p2 + p3;
                    s_ct += (float)(t.x + t.y + t.z + t.w);
                }
            } else { vp.x = vp.y = PINF2; vt.x = vt.y = PINF2; }
            // half 1 (px gxb+4..gxb+7)
            if (rin && (!BORDER || ((unsigned)(gxb + 4) < W))) {
                float4 l = *(const float4*)(lg + rowoff + gxb + 4);
                int4   t = *(const int4*)(tp + rowoff + gxb + 4);
                float p0 = 1.0f / (1.0f + __expf(-l.x));
                float p1 = 1.0f / (1.0f + __expf(-l.y));
                float p2 = 1.0f / (1.0f + __expf(-l.z));
                float p3 = 1.0f / (1.0f + __expf(-l.w));
                vp.z = pack2(p0, p1); vp.w = pack2(p2, p3);
                vt.z = pack2((float)t.x, (float)t.y);
                vt.w = pack2((float)t.z, (float)t.w);
                if (center) {
                    s_inter += p0*(float)t.x + p1*(float)t.y + p2*(float)t.z + p3*(float)t.w;
                    s_cp += p0 + p1 + p2 + p3;
                    s_ct += (float)(t.x + t.y + t.z + t.w);
                }
            } else { vp.z = vp.w = PINF2; vt.z = vt.w = PINF2; }
        } else {
            vp = make_uint4(PINF2, PINF2, PINF2, PINF2);
            vt = vp;
            B[idx] = vp;   // guards must be PINF in ping-pong buffers too
            Db[idx] = vt;
        }
        A[idx]  = vp;
        Cb[idx] = vt;
    }
    {
        float b;
        b = blockReduceSum(s_inter, red);
        if (tid == 0) atomicAdd(&g_acc[0], (double)b);
        b = blockReduceSum(s_cp + s_ct, red);
        if (tid == 0) atomicAdd(&g_acc[1], (double)b);
        b = blockReduceSum(s_ct, red);
        if (tid == 0) atomicAdd(&g_acc[2], (double)b);
    }
    __syncthreads();

    // ---- pass-1 mapping: 20 uint4 cols x 50 groups x 3 rows
    const int u1 = 1 + tid % 20;
    const int g1 = tid / 20;
    const int rs3 = 1 + 3 * g1;
    const bool g1ok = g1 < 50;
    bool xo0 = false, xo1 = false, xo2 = false, xo3 = false;
    if (BORDER) {
        int xb = x0 - 16 + 8 * (u1 - 1);
        xo0 = (unsigned)(xb + 0) >= W;
        xo1 = (unsigned)(xb + 2) >= W;
        xo2 = (unsigned)(xb + 4) >= W;
        xo3 = (unsigned)(xb + 6) >= W;
    }

    // ---- pass-2 mapping: 16 uint4 cols x 64 groups x 2 rows (center only)
    const int u2 = 3 + (tid & 15);
    const int yb = 12 + 2 * (tid >> 4);

    float sk_o[16], sk_t[16];
    #pragma unroll
    for (int i = 0; i < 16; i++) { sk_o[i] = 0.f; sk_t[i] = 0.f; }

    uint4 *cO = A, *nO = B, *cT = Cb, *nT = Db;

    for (int j = 0; j < 11; j++) {
        const int m = 11 - j;
        const int lo = 12 - m, hi = 140 + m;
        int start = rs3 > lo ? rs3 : lo;
        int end   = (rs3 + 3 < hi) ? rs3 + 3 : hi;
        bool colact = (8 * (u1 - 1) < 144 + m) && (8 * u1 > 16 - m);
        if (g1ok && colact && start < end) {
            erode_pass<BORDER>(cO, nO, u1, start, end, xo0, xo1, xo2, xo3, y0);
            erode_pass<BORDER>(cT, nT, u1, start, end, xo0, xo1, xo2, xo3, y0);
        }
        __syncthreads();

        dilate_skel<BORDER>(cO, nO, u2, yb, sk_o);
        dilate_skel<BORDER>(cT, nT, u2, yb, sk_t);
        __syncthreads();

        uint4* t;
        t = cO; cO = nO; nO = t;
        t = cT; cT = nT; nT = t;
    }

    // ---- final skeleton sums (cross-chain products in-register)
    float sot = 0.f, so = 0.f, st = 0.f;
    #pragma unroll
    for (int i = 0; i < 16; i++) {
        sot += sk_o[i] * sk_t[i];
        so  += sk_o[i];
        st  += sk_t[i];
    }
    float b;
    b = blockReduceSum(sot, red); if (tid == 0) atomicAdd(&g_acc[3], (double)b);
    b = blockReduceSum(so,  red); if (tid == 0) atomicAdd(&g_acc[4], (double)b);
    b = blockReduceSum(st,  red); if (tid == 0) atomicAdd(&g_acc[5], (double)b);
}

// ---------------------------------------------------------------------------
__global__ void __launch_bounds__(NT, 1)
fused_kernel(const float* __restrict__ logits, const int* __restrict__ target,
             float* __restrict__ out)
{
    extern __shared__ uint4 smem4[];
    __shared__ float red[32];
    uint4* A  = smem4;
    uint4* B  = A + BUF_U4;
    uint4* Cb = B + BUF_U4;
    uint4* Db = Cb + BUF_U4;
    bool border = (blockIdx.x == 0) | (blockIdx.x == gridDim.x - 1) |
                  (blockIdx.y == 0) | (blockIdx.y == gridDim.y - 1);
    if (border) tile_run<true >(logits, target, A, B, Cb, Db, red);
    else        tile_run<false>(logits, target, A, B, Cb, Db, red);

    // last block finalizes and resets accumulators for the next graph replay
    if (threadIdx.x == 0) {
        __threadfence();
        unsigned done = atomicAdd(&g_done, 1u);
        if (done == NBLOCKS - 1) {
            double inter = atomicAdd(&g_acc[0], 0.0);
            double card  = atomicAdd(&g_acc[1], 0.0);
            double sumt  = atomicAdd(&g_acc[2], 0.0);
            double sot   = atomicAdd(&g_acc[3], 0.0);
            double so    = atomicAdd(&g_acc[4], 0.0);
            double stk   = atomicAdd(&g_acc[5], 0.0);
            double score = (2.0 * inter + 1.0) / fmax(card + 1.0, 1e-7);
            double dice  = (1.0 - score) * (sumt > 0.0 ? 1.0 : 0.0);
            double tprec = (sot + 1.0) / (so + 1.0);
            double tsens = (sot + 1.0) / (stk + 1.0);
            double cs    = 2.0 * (tprec * tsens) / (tprec + tsens);
            double cl    = (1.0 - cs) * (stk > 0.0 ? 1.0 : 0.0);
            out[0] = (float)(0.5 * dice + 0.5 * cl);
            g_acc[0] = 0.0; g_acc[1] = 0.0; g_acc[2] = 0.0;
            g_acc[3] = 0.0; g_acc[4] = 0.0; g_acc[5] = 0.0;
            __threadfence();
            g_done = 0;
        }
    }
}

// ---------------------------------------------------------------------------
extern "C" void kernel_launch(void* const* d_in, const int* in_sizes, int n_in,
                              void* d_out, int out_size) {
    (void)in_sizes; (void)n_in; (void)out_size;
    const float* logits = (const float*)d_in[0];
    const int*   target = (const int*)d_in[1];

    cudaFuncSetAttribute(fused_kernel,
                         cudaFuncAttributeMaxDynamicSharedMemorySize,
                         4 * BUF_U4 * (int)sizeof(uint4));

    dim3 grid(W / 128, H / 128, 8);
    fused_kernel<<<grid, NT, 4 * BUF_U4 * sizeof(uint4)>>>(logits, target, (float*)d_out);
}

// round 6
// speedup vs baseline: 4.3996x; 1.4294x over previous
#include <cuda_runtime.h>
#include <cuda_fp16.h>

#define H 1024
#define W 1024
#define PLANE_SZ (H * W)

#define NT 1024
#define ROWS 152               // 128 + 2*12 halo rows
#define RW 22                  // uint4 per row: 20 data (160 px, x-halo 16) + 2 guards
#define BUF_U4 (ROWS * RW)     // 3344 uint4 per fp16 buffer
#define PINF2 0x7C007C00u
#define NBLOCKS 512

// bit buffers: 1 bit/px, 5 words per row (160 px), dense stride 5
#define BST 5
#define BBUF (ROWS * BST)      // 760 words

__device__ double g_acc[6];
__device__ unsigned g_done;

// ---------------------------------------------------------------------------
__device__ __forceinline__ unsigned hmin2u(unsigned a, unsigned b) {
    __half2 r = __hmin2(*(__half2*)&a, *(__half2*)&b);
    return *(unsigned*)&r;
}
__device__ __forceinline__ unsigned hmax2u(unsigned a, unsigned b) {
    __half2 r = __hmax2(*(__half2*)&a, *(__half2*)&b);
    return *(unsigned*)&r;
}
__device__ __forceinline__ unsigned hsub2u(unsigned a, unsigned b) {
    __half2 r = __hsub2(*(__half2*)&a, *(__half2*)&b);
    return *(unsigned*)&r;
}
__device__ __forceinline__ unsigned pack2(float a, float b) {
    __half2 h = __floats2half2_rn(a, b);
    return *(unsigned*)&h;
}
__device__ __forceinline__ float2 unpack2(unsigned v) {
    return __half22float2(*(__half2*)&v);
}
__device__ __forceinline__ unsigned remap2u(unsigned v) {
    unsigned m = __vcmpeq2(v, PINF2) & 0x80008000u;
    return v | m;
}
// bits i valid iff 0 <= startpx + i < W
__device__ __forceinline__ unsigned xmask_f(int startpx) {
    unsigned m = ~0u;
    if (startpx < 0) { int k = -startpx; m = (k >= 32) ? 0u : (m << k); }
    int k2 = startpx + 32 - W;
    if (k2 > 0) m &= (k2 >= 32) ? 0u : (~0u >> k2);
    return m;
}

__device__ __forceinline__ float blockReduceSum(float v, float* red) {
    #pragma unroll
    for (int o = 16; o > 0; o >>= 1) v += __shfl_down_sync(0xffffffffu, v, o);
    int lane = threadIdx.x & 31;
    int wid  = threadIdx.x >> 5;
    if (lane == 0) red[wid] = v;
    __syncthreads();
    v = (threadIdx.x < 32) ? red[threadIdx.x] : 0.0f;
    if (wid == 0) {
        #pragma unroll
        for (int o = 16; o > 0; o >>= 1) v += __shfl_down_sync(0xffffffffu, v, o);
    }
    __syncthreads();
    return v;
}

// ---------------------------------------------------------------------------
// fp16 erode (5-pt cross min) rows [start,end), cur -> nxt
template<bool BORDER>
__device__ __forceinline__ void erode_pass(const uint4* __restrict__ cur,
                                           uint4* __restrict__ nxt,
                                           int u1, int start, int end,
                                           bool xo0, bool xo1, bool xo2, bool xo3,
                                           int y0)
{
    const unsigned* cur32 = (const unsigned*)cur;
    int base = start * RW + u1;
    uint4 a = cur[base - RW];
    uint4 b = cur[base];
    for (int r = start; r < end; r++) {
        uint4 c = cur[base + RW];
        unsigned Lh = cur32[4 * base - 1];
        unsigned Rh = cur32[4 * base + 4];
        unsigned P0 = __byte_perm(Lh,  b.x, 0x5432);
        unsigned P1 = __byte_perm(b.x, b.y, 0x5432);
        unsigned P2 = __byte_perm(b.y, b.z, 0x5432);
        unsigned P3 = __byte_perm(b.z, b.w, 0x5432);
        unsigned P4 = __byte_perm(b.w, Rh, 0x5432);
        uint4 e;
        e.x = hmin2u(hmin2u(a.x, c.x), hmin2u(b.x, hmin2u(P0, P1)));
        e.y = hmin2u(hmin2u(a.y, c.y), hmin2u(b.y, hmin2u(P1, P2)));
        e.z = hmin2u(hmin2u(a.z, c.z), hmin2u(b.z, hmin2u(P2, P3)));
        e.w = hmin2u(hmin2u(a.w, c.w), hmin2u(b.w, hmin2u(P3, P4)));
        if (BORDER) {
            bool yo = ((unsigned)(y0 - 12 + r) >= H);
            if (xo0 | yo) e.x = PINF2;
            if (xo1 | yo) e.y = PINF2;
            if (xo2 | yo) e.z = PINF2;
            if (xo3 | yo) e.w = PINF2;
        }
        nxt[base] = e;
        a = b; b = c; base += RW;
    }
}

template<bool BORDER>
__device__ __forceinline__ uint4 rowmax_fn(const uint4* __restrict__ nxt,
                                           const unsigned* __restrict__ nxt32,
                                           int base)
{
    uint4 C = nxt[base];
    unsigned Lh = nxt32[4 * base - 1];
    unsigned Rh = nxt32[4 * base + 4];
    if (BORDER) {
        C.x = remap2u(C.x); C.y = remap2u(C.y); C.z = remap2u(C.z); C.w = remap2u(C.w);
        Lh = remap2u(Lh); Rh = remap2u(Rh);
    }
    unsigned P0 = __byte_perm(Lh,  C.x, 0x5432);
    unsigned P1 = __byte_perm(C.x, C.y, 0x5432);
    unsigned P2 = __byte_perm(C.y, C.z, 0x5432);
    unsigned P3 = __byte_perm(C.z, C.w, 0x5432);
    unsigned P4 = __byte_perm(C.w, Rh, 0x5432);
    uint4 h;
    h.x = hmax2u(C.x, hmax2u(P0, P1));
    h.y = hmax2u(C.y, hmax2u(P1, P2));
    h.z = hmax2u(C.z, hmax2u(P2, P3));
    h.w = hmax2u(C.w, hmax2u(P3, P4));
    return h;
}

template<bool BORDER>
__device__ __forceinline__ void dilate_skel(const uint4* __restrict__ cur,
                                            const uint4* __restrict__ nxt,
                                            int u2, int yb, float* sk)
{
    const unsigned* nxt32 = (const unsigned*)nxt;
    uint4 h0 = rowmax_fn<BORDER>(nxt, nxt32, (yb - 1) * RW + u2);
    uint4 h1 = rowmax_fn<BORDER>(nxt, nxt32,  yb      * RW + u2);
    #pragma unroll
    for (int i = 0; i < 2; i++) {
        uint4 h2 = rowmax_fn<BORDER>(nxt, nxt32, (yb + 1 + i) * RW + u2);
        uint4 av = cur[(yb + i) * RW + u2];
        unsigned dw, del; float2 f; float s;

        dw = hmax2u(h0.x, hmax2u(h1.x, h2.x));
        del = hmax2u(hsub2u(av.x, dw), 0u); f = unpack2(del);
        s = sk[i*8+0]; sk[i*8+0] = s + fmaxf(fmaf(-s, f.x, f.x), 0.f);
        s = sk[i*8+1]; sk[i*8+1] = s + fmaxf(fmaf(-s, f.y, f.y), 0.f);

        dw = hmax2u(h0.y, hmax2u(h1.y, h2.y));
        del = hmax2u(hsub2u(av.y, dw), 0u); f = unpack2(del);
        s = sk[i*8+2]; sk[i*8+2] = s + fmaxf(fmaf(-s, f.x, f.x), 0.f);
        s = sk[i*8+3]; sk[i*8+3] = s + fmaxf(fmaf(-s, f.y, f.y), 0.f);

        dw = hmax2u(h0.z, hmax2u(h1.z, h2.z));
        del = hmax2u(hsub2u(av.z, dw), 0u); f = unpack2(del);
        s = sk[i*8+4]; sk[i*8+4] = s + fmaxf(fmaf(-s, f.x, f.x), 0.f);
        s = sk[i*8+5]; sk[i*8+5] = s + fmaxf(fmaf(-s, f.y, f.y), 0.f);

        dw = hmax2u(h0.w, hmax2u(h1.w, h2.w));
        del = hmax2u(hsub2u(av.w, dw), 0u); f = unpack2(del);
        s = sk[i*8+6]; sk[i*8+6] = s + fmaxf(fmaf(-s, f.x, f.x), 0.f);
        s = sk[i*8+7]; sk[i*8+7] = s + fmaxf(fmaf(-s, f.y, f.y), 0.f);

        h0 = h1; h1 = h2;
    }
}

// ---------------------------------------------------------------------------
template<bool BORDER>
__device__ __forceinline__ void tile_run(const float* __restrict__ logits,
                                         const int* __restrict__ target,
                                         uint4* A, uint4* B,
                                         unsigned* Tc, unsigned* Tn, unsigned* SK,
                                         float* red, float* out)
{
    const int p8 = blockIdx.z;
    const int x0 = blockIdx.x * 128;
    const int y0 = blockIdx.y * 128;
    const int tid = threadIdx.x;
    const float* lg = logits + (size_t)p8 * PLANE_SZ;
    const int*   tp = target + (size_t)p8 * PLANE_SZ;

    // ---- phase 0: init bit buffer (invalid px = 1) ----
    if (tid < BBUF) {
        int r = tid / BST, w = tid - r * BST;
        unsigned V;
        if (BORDER) {
            int gy = y0 - 12 + r;
            V = ((unsigned)gy < H) ? xmask_f(x0 - 16 + 32 * w) : 0u;
        } else V = ~0u;
        Tc[tid] = ~V;
    }
    __syncthreads();

    // ---- load: prob -> fp16 A, target -> bits (atomicOr), dice partials ----
    float s_inter = 0.f, s_cp = 0.f, s_ct = 0.f;
    for (int idx = tid; idx < BUF_U4; idx += NT) {
        int r = idx / RW;
        int u = idx - r * RW;
        uint4 vp;
        bool guard = (u == 0) | (u == RW - 1);
        if (!guard) {
            int gy = y0 - 12 + r;
            int gxb = x0 - 16 + 8 * (u - 1);
            bool rin = !BORDER || ((unsigned)gy < H);
            size_t rowoff = (size_t)gy * W;
            bool center = (u >= 3) & (u < 19) & (r >= 12) & (r < 140);
            unsigned tbits = 0;
            if (rin && (!BORDER || ((unsigned)gxb < W))) {
                float4 l = *(const float4*)(lg + rowoff + gxb);
                int4   t = *(const int4*)(tp + rowoff + gxb);
                float p0 = 1.0f / (1.0f + __expf(-l.x));
                float p1 = 1.0f / (1.0f + __expf(-l.y));
                float p2 = 1.0f / (1.0f + __expf(-l.z));
                float p3 = 1.0f / (1.0f + __expf(-l.w));
                vp.x = pack2(p0, p1); vp.y = pack2(p2, p3);
                tbits |= (unsigned)t.x | ((unsigned)t.y << 1) |
                         ((unsigned)t.z << 2) | ((unsigned)t.w << 3);
                if (center) {
                    s_inter += p0*(float)t.x + p1*(float)t.y + p2*(float)t.z + p3*(float)t.w;
                    s_cp += p0 + p1 + p2 + p3;
                    s_ct += (float)(t.x + t.y + t.z + t.w);
                }
            } else { vp.x = vp.y = PINF2; }
            if (rin && (!BORDER || ((unsigned)(gxb + 4) < W))) {
                float4 l = *(const float4*)(lg + rowoff + gxb + 4);
                int4   t = *(const int4*)(tp + rowoff + gxb + 4);
                float p0 = 1.0f / (1.0f + __expf(-l.x));
                float p1 = 1.0f / (1.0f + __expf(-l.y));
                float p2 = 1.0f / (1.0f + __expf(-l.z));
                float p3 = 1.0f / (1.0f + __expf(-l.w));
                vp.z = pack2(p0, p1); vp.w = pack2(p2, p3);
                tbits |= ((unsigned)t.x << 4) | ((unsigned)t.y << 5) |
                         ((unsigned)t.z << 6) | ((unsigned)t.w << 7);
                if (center) {
                    s_inter += p0*(float)t.x + p1*(float)t.y + p2*(float)t.z + p3*(float)t.w;
                    s_cp += p0 + p1 + p2 + p3;
                    s_ct += (float)(t.x + t.y + t.z + t.w);
                }
            } else { vp.z = vp.w = PINF2; }
            if (tbits) {
                int du = u - 1;
                atomicOr(&Tc[r * BST + (du >> 2)], tbits << ((du & 3) * 8));
            }
        } else {
            vp = make_uint4(PINF2, PINF2, PINF2, PINF2);
            B[idx] = vp;
        }
        A[idx] = vp;
    }
    __syncthreads();

    // ---- pass-1 fp16 mapping: 20 cols x 50 groups x 3 rows ----
    const int u1 = 1 + tid % 20;
    const int g1 = tid / 20;
    const int rs3 = 1 + 3 * g1;
    const bool g1ok = g1 < 50;
    bool xo0 = false, xo1 = false, xo2 = false, xo3 = false;
    if (BORDER) {
        int xb = x0 - 16 + 8 * (u1 - 1);
        xo0 = (unsigned)(xb + 0) >= W;
        xo1 = (unsigned)(xb + 2) >= W;
        xo2 = (unsigned)(xb + 4) >= W;
        xo3 = (unsigned)(xb + 6) >= W;
    }

    // ---- pass-1 bit mapping: rows 1..150 x 5 words (750 threads) ----
    const bool be_act = tid < 750;
    const int br = 1 + tid / BST;
    const int bw = tid % BST;
    const int bidx = br * BST + bw;
    unsigned be_nv = 0;
    if (BORDER && be_act) {
        int gy = y0 - 12 + br;
        unsigned V = ((unsigned)gy < H) ? xmask_f(x0 - 16 + 32 * bw) : 0u;
        be_nv = ~V;
    }

    // ---- pass-2 fp16 mapping ----
    const int u2 = 3 + (tid & 15);
    const int yb = 12 + 2 * (tid >> 4);

    // ---- pass-2 bit mapping: rows 12..139 x 5 words (640 threads) ----
    const bool bd_act = tid < 640;
    const int dr = 12 + tid / BST;
    const int dw2 = tid % BST;
    const int didx = dr * BST + dw2;
    unsigned m0 = ~0u, mm1 = ~0u, mp1 = ~0u;
    bool upok = true, dnok = true;
    if (BORDER && bd_act) {
        m0  = xmask_f(x0 - 16 + 32 * dw2);
        mm1 = (dw2 > 0) ? xmask_f(x0 - 16 + 32 * (dw2 - 1)) : 0u;
        mp1 = (dw2 < 4) ? xmask_f(x0 - 16 + 32 * (dw2 + 1)) : 0u;
        int gy = y0 - 12 + dr;
        upok = (gy - 1) >= 0;
        dnok = (gy + 1) < H;
    }
    unsigned skw = 0;

    float sk_o[16];
    #pragma unroll
    for (int i = 0; i < 16; i++) sk_o[i] = 0.f;

    uint4 *cO = A, *nO = B;
    unsigned *cT = Tc, *nT = Tn;

    for (int j = 0; j < 11; j++) {
        const int m = 11 - j;
        // fp16 erode (shrinking region)
        {
            const int lo = 12 - m, hi = 140 + m;
            int start = rs3 > lo ? rs3 : lo;
            int end   = (rs3 + 3 < hi) ? rs3 + 3 : hi;
            bool colact = (8 * (u1 - 1) < 144 + m) && (8 * u1 > 16 - m);
            if (g1ok && colact && start < end)
                erode_pass<BORDER>(cO, nO, u1, start, end, xo0, xo1, xo2, xo3, y0);
        }
        // bit erode (full region, exact)
        if (be_act) {
            unsigned xc = cT[bidx];
            unsigned xu = cT[bidx - BST];
            unsigned xd = cT[bidx + BST];
            unsigned xl = (bw > 0) ? cT[bidx - 1] : ~0u;
            unsigned xr = (bw < 4) ? cT[bidx + 1] : ~0u;
            unsigned L = (xc << 1) | (xl >> 31);
            unsigned R = (xc >> 1) | (xr << 31);
            unsigned e = xc & xu & xd & L & R;
            if (BORDER) e |= be_nv;
            nT[bidx] = e;
        }
        __syncthreads();

        // fp16 dilate + delta + sk
        dilate_skel<BORDER>(cO, nO, u2, yb, sk_o);
        // bit dilate + delta + sk
        if (bd_act) {
            unsigned d = 0;
            #pragma unroll
            for (int rr = -1; rr <= 1; rr++) {
                bool ok = (rr == -1) ? upok : ((rr == 1) ? dnok : true);
                int bse = (dr + rr) * BST + dw2;
                unsigned c  = nT[bse] & m0;
                unsigned l  = (dw2 > 0) ? (nT[bse - 1] & mm1) : 0u;
                unsigned rt = (dw2 < 4) ? (nT[bse + 1] & mp1) : 0u;
                unsigned rowv = c | ((c << 1) | (l >> 31)) | ((c >> 1) | (rt << 31));
                if (BORDER && !ok) rowv = 0u;
                d |= rowv;
            }
            unsigned ecur = cT[didx] & m0;
            skw |= ecur & ~d;
        }
        __syncthreads();

        uint4* t4; t4 = cO; cO = nO; nO = t4;
        unsigned* tb; tb = cT; cT = nT; nT = tb;
    }

    // ---- publish sk_t bits, then cross-chain sums ----
    float s_st = 0.f;
    if (bd_act) {
        SK[didx] = skw;
        unsigned cmask = (dw2 == 0) ? 0xFFFF0000u : ((dw2 == 4) ? 0x0000FFFFu : ~0u);
        s_st = (float)__popc(skw & cmask);
    }
    __syncthreads();

    float sot = 0.f, so = 0.f;
    {
        const int du = u2 - 1;
        const int wd = du >> 2;
        const int bp = (du & 3) * 8;
        #pragma unroll
        for (int i = 0; i < 2; i++) {
            unsigned bbyte = (SK[(yb + i) * BST + wd] >> bp) & 0xffu;
            #pragma unroll
            for (int k = 0; k < 8; k++) {
                float o = sk_o[i * 8 + k];
                so += o;
                if ((bbyte >> k) & 1u) sot += o;
            }
        }
    }

    float b;
    b = blockReduceSum(s_inter, red);      if (tid == 0) atomicAdd(&g_acc[0], (double)b);
    b = blockReduceSum(s_cp + s_ct, red);  if (tid == 0) atomicAdd(&g_acc[1], (double)b);
    b = blockReduceSum(s_ct, red);         if (tid == 0) atomicAdd(&g_acc[2], (double)b);
    b = blockReduceSum(sot, red);          if (tid == 0) atomicAdd(&g_acc[3], (double)b);
    b = blockReduceSum(so,  red);          if (tid == 0) atomicAdd(&g_acc[4], (double)b);
    b = blockReduceSum(s_st, red);         if (tid == 0) atomicAdd(&g_acc[5], (double)b);

    if (tid == 0) {
        __threadfence();
        unsigned done = atomicAdd(&g_done, 1u);
        if (done == NBLOCKS - 1) {
            double inter = atomicAdd(&g_acc[0], 0.0);
            double card  = atomicAdd(&g_acc[1], 0.0);
            double sumt  = atomicAdd(&g_acc[2], 0.0);
            double sot2  = atomicAdd(&g_acc[3], 0.0);
            double so2   = atomicAdd(&g_acc[4], 0.0);
            double stk   = atomicAdd(&g_acc[5], 0.0);
            double score = (2.0 * inter + 1.0) / fmax(card + 1.0, 1e-7);
            double dice  = (1.0 - score) * (sumt > 0.0 ? 1.0 : 0.0);
            double tprec = (sot2 + 1.0) / (so2 + 1.0);
            double tsens = (sot2 + 1.0) / (stk + 1.0);
            double cs    = 2.0 * (tprec * tsens) / (tprec + tsens);
            double cl    = (1.0 - cs) * (stk > 0.0 ? 1.0 : 0.0);
            out[0] = (float)(0.5 * dice + 0.5 * cl);
            g_acc[0] = 0.0; g_acc[1] = 0.0; g_acc[2] = 0.0;
            g_acc[3] = 0.0; g_acc[4] = 0.0; g_acc[5] = 0.0;
            __threadfence();
            g_done = 0;
        }
    }
}

// ---------------------------------------------------------------------------
__global__ void __launch_bounds__(NT, 1)
fused_kernel(const float* __restrict__ logits, const int* __restrict__ target,
             float* __restrict__ out)
{
    extern __shared__ uint4 smem4[];
    __shared__ float red[32];
    uint4* A = smem4;
    uint4* B = A + BUF_U4;
    unsigned* bits = (unsigned*)(B + BUF_U4);
    unsigned* Tc = bits;
    unsigned* Tn = bits + BBUF;
    unsigned* SK = bits + 2 * BBUF;
    bool border = (blockIdx.x == 0) | (blockIdx.x == gridDim.x - 1) |
                  (blockIdx.y == 0) | (blockIdx.y == gridDim.y - 1);
    if (border) tile_run<true >(logits, target, A, B, Tc, Tn, SK, red, out);
    else        tile_run<false>(logits, target, A, B, Tc, Tn, SK, red, out);
}

// ---------------------------------------------------------------------------
extern "C" void kernel_launch(void* const* d_in, const int* in_sizes, int n_in,
                              void* d_out, int out_size) {
    (void)in_sizes; (void)n_in; (void)out_size;
    const float* logits = (const float*)d_in[0];
    const int*   target = (const int*)d_in[1];

    const int smem_bytes = 2 * BUF_U4 * (int)sizeof(uint4) + 3 * BBUF * (int)sizeof(unsigned);
    cudaFuncSetAttribute(fused_kernel,
                         cudaFuncAttributeMaxDynamicSharedMemorySize, smem_bytes);

    dim3 grid(W / 128, H / 128, 8);
    fused_kernel<<<grid, NT, smem_bytes>>>(logits, target, (float*)d_out);
}

// round 7
// speedup vs baseline: 4.8786x; 1.1089x over previous
#include <cuda_runtime.h>
#include <cuda_fp16.h>

#define H 1024
#define W 1024
#define PLANE_SZ (H * W)

#define TX 128
#define TY 64
#define NT 512
#define ROWS (TY + 24)         // 88: 64 + 2*12 halo rows
#define RW 22                  // uint4 per row: 20 data (160 px) + 2 guards
#define BUF_U4 (ROWS * RW)     // 1936 uint4 per fp16 buffer
#define PINF2 0x7C007C00u
#define NBLOCKS 1024           // 8 x 16 x 8

#define BST 5
#define BBUF (ROWS * BST)      // 440 words per bit buffer

__device__ double g_acc[6];
__device__ unsigned g_done;

// ---------------------------------------------------------------------------
__device__ __forceinline__ unsigned hmin2u(unsigned a, unsigned b) {
    __half2 r = __hmin2(*(__half2*)&a, *(__half2*)&b);
    return *(unsigned*)&r;
}
__device__ __forceinline__ unsigned hmax2u(unsigned a, unsigned b) {
    __half2 r = __hmax2(*(__half2*)&a, *(__half2*)&b);
    return *(unsigned*)&r;
}
__device__ __forceinline__ unsigned hsub2u(unsigned a, unsigned b) {
    __half2 r = __hsub2(*(__half2*)&a, *(__half2*)&b);
    return *(unsigned*)&r;
}
__device__ __forceinline__ unsigned pack2(float a, float b) {
    __half2 h = __floats2half2_rn(a, b);
    return *(unsigned*)&h;
}
__device__ __forceinline__ float2 unpack2(unsigned v) {
    return __half22float2(*(__half2*)&v);
}
__device__ __forceinline__ unsigned remap2u(unsigned v) {
    unsigned m = __vcmpeq2(v, PINF2) & 0x80008000u;
    return v | m;
}
__device__ __forceinline__ unsigned xmask_f(int startpx) {
    unsigned m = ~0u;
    if (startpx < 0) { int k = -startpx; m = (k >= 32) ? 0u : (m << k); }
    int k2 = startpx + 32 - W;
    if (k2 > 0) m &= (k2 >= 32) ? 0u : (~0u >> k2);
    return m;
}

__device__ __forceinline__ float blockReduceSum(float v, float* red) {
    #pragma unroll
    for (int o = 16; o > 0; o >>= 1) v += __shfl_down_sync(0xffffffffu, v, o);
    int lane = threadIdx.x & 31;
    int wid  = threadIdx.x >> 5;
    if (lane == 0) red[wid] = v;
    __syncthreads();
    v = (threadIdx.x < 16) ? red[threadIdx.x] : 0.0f;
    if (wid == 0) {
        #pragma unroll
        for (int o = 8; o > 0; o >>= 1) v += __shfl_down_sync(0xffffffffu, v, o);
    }
    __syncthreads();
    return v;
}

// ---------------------------------------------------------------------------
template<bool BORDER>
__device__ __forceinline__ void erode_pass(const uint4* __restrict__ cur,
                                           uint4* __restrict__ nxt,
                                           int u1, int start, int end,
                                           bool xo0, bool xo1, bool xo2, bool xo3,
                                           int y0)
{
    const unsigned* cur32 = (const unsigned*)cur;
    int base = start * RW + u1;
    uint4 a = cur[base - RW];
    uint4 b = cur[base];
    for (int r = start; r < end; r++) {
        uint4 c = cur[base + RW];
        unsigned Lh = cur32[4 * base - 1];
        unsigned Rh = cur32[4 * base + 4];
        unsigned P0 = __byte_perm(Lh,  b.x, 0x5432);
        unsigned P1 = __byte_perm(b.x, b.y, 0x5432);
        unsigned P2 = __byte_perm(b.y, b.z, 0x5432);
        unsigned P3 = __byte_perm(b.z, b.w, 0x5432);
        unsigned P4 = __byte_perm(b.w, Rh, 0x5432);
        uint4 e;
        e.x = hmin2u(hmin2u(a.x, c.x), hmin2u(b.x, hmin2u(P0, P1)));
        e.y = hmin2u(hmin2u(a.y, c.y), hmin2u(b.y, hmin2u(P1, P2)));
        e.z = hmin2u(hmin2u(a.z, c.z), hmin2u(b.z, hmin2u(P2, P3)));
        e.w = hmin2u(hmin2u(a.w, c.w), hmin2u(b.w, hmin2u(P3, P4)));
        if (BORDER) {
            bool yo = ((unsigned)(y0 - 12 + r) >= H);
            if (xo0 | yo) e.x = PINF2;
            if (xo1 | yo) e.y = PINF2;
            if (xo2 | yo) e.z = PINF2;
            if (xo3 | yo) e.w = PINF2;
        }
        nxt[base] = e;
        a = b; b = c; base += RW;
    }
}

template<bool BORDER>
__device__ __forceinline__ uint4 rowmax_fn(const uint4* __restrict__ nxt,
                                           const unsigned* __restrict__ nxt32,
                                           int base)
{
    uint4 C = nxt[base];
    unsigned Lh = nxt32[4 * base - 1];
    unsigned Rh = nxt32[4 * base + 4];
    if (BORDER) {
        C.x = remap2u(C.x); C.y = remap2u(C.y); C.z = remap2u(C.z); C.w = remap2u(C.w);
        Lh = remap2u(Lh); Rh = remap2u(Rh);
    }
    unsigned P0 = __byte_perm(Lh,  C.x, 0x5432);
    unsigned P1 = __byte_perm(C.x, C.y, 0x5432);
    unsigned P2 = __byte_perm(C.y, C.z, 0x5432);
    unsigned P3 = __byte_perm(C.z, C.w, 0x5432);
    unsigned P4 = __byte_perm(C.w, Rh, 0x5432);
    uint4 h;
    h.x = hmax2u(C.x, hmax2u(P0, P1));
    h.y = hmax2u(C.y, hmax2u(P1, P2));
    h.z = hmax2u(C.z, hmax2u(P2, P3));
    h.w = hmax2u(C.w, hmax2u(P3, P4));
    return h;
}

// dilate 3x3 of dil, delta = relu(av - d), sk update; 2 rows x 8 px
template<bool BORDER>
__device__ __forceinline__ void dilate_skel(const uint4* __restrict__ av_buf,
                                            const uint4* __restrict__ dil,
                                            int u2, int yb, float* sk)
{
    const unsigned* dil32 = (const unsigned*)dil;
    uint4 h0 = rowmax_fn<BORDER>(dil, dil32, (yb - 1) * RW + u2);
    uint4 h1 = rowmax_fn<BORDER>(dil, dil32,  yb      * RW + u2);
    #pragma unroll
    for (int i = 0; i < 2; i++) {
        uint4 h2 = rowmax_fn<BORDER>(dil, dil32, (yb + 1 + i) * RW + u2);
        uint4 av = av_buf[(yb + i) * RW + u2];
        unsigned dw, del; float2 f; float s;

        dw = hmax2u(h0.x, hmax2u(h1.x, h2.x));
        del = hmax2u(hsub2u(av.x, dw), 0u); f = unpack2(del);
        s = sk[i*8+0]; sk[i*8+0] = s + fmaxf(fmaf(-s, f.x, f.x), 0.f);
        s = sk[i*8+1]; sk[i*8+1] = s + fmaxf(fmaf(-s, f.y, f.y), 0.f);

        dw = hmax2u(h0.y, hmax2u(h1.y, h2.y));
        del = hmax2u(hsub2u(av.y, dw), 0u); f = unpack2(del);
        s = sk[i*8+2]; sk[i*8+2] = s + fmaxf(fmaf(-s, f.x, f.x), 0.f);
        s = sk[i*8+3]; sk[i*8+3] = s + fmaxf(fmaf(-s, f.y, f.y), 0.f);

        dw = hmax2u(h0.z, hmax2u(h1.z, h2.z));
        del = hmax2u(hsub2u(av.z, dw), 0u); f = unpack2(del);
        s = sk[i*8+4]; sk[i*8+4] = s + fmaxf(fmaf(-s, f.x, f.x), 0.f);
        s = sk[i*8+5]; sk[i*8+5] = s + fmaxf(fmaf(-s, f.y, f.y), 0.f);

        dw = hmax2u(h0.w, hmax2u(h1.w, h2.w));
        del = hmax2u(hsub2u(av.w, dw), 0u); f = unpack2(del);
        s = sk[i*8+6]; sk[i*8+6] = s + fmaxf(fmaf(-s, f.x, f.x), 0.f);
        s = sk[i*8+7]; sk[i*8+7] = s + fmaxf(fmaf(-s, f.y, f.y), 0.f);

        h0 = h1; h1 = h2;
    }
}

// ---------------------------------------------------------------------------
template<bool BORDER>
__device__ __forceinline__ void tile_run(const float* __restrict__ logits,
                                         const int* __restrict__ target,
                                         uint4* A, uint4* Bf, uint4* Cf,
                                         unsigned* T0, unsigned* T1, unsigned* T2,
                                         unsigned* SK,
                                         float* red, float* out)
{
    const int p8 = blockIdx.z;
    const int x0 = blockIdx.x * TX;
    const int y0 = blockIdx.y * TY;
    const int tid = threadIdx.x;
    const float* lg = logits + (size_t)p8 * PLANE_SZ;
    const int*   tp = target + (size_t)p8 * PLANE_SZ;

    // ---- init bit buffer (invalid px = 1)
    if (tid < BBUF) {
        int r = tid / BST, w = tid - r * BST;
        unsigned V;
        if (BORDER) {
            int gy = y0 - 12 + r;
            V = ((unsigned)gy < H) ? xmask_f(x0 - 16 + 32 * w) : 0u;
        } else V = ~0u;
        T0[tid] = ~V;
    }
    __syncthreads();

    // ---- load: prob -> fp16 A, target bits -> T0 (atomicOr), dice partials
    float s_inter = 0.f, s_cp = 0.f, s_ct = 0.f;
    for (int idx = tid; idx < BUF_U4; idx += NT) {
        int r = idx / RW;
        int u = idx - r * RW;
        uint4 vp;
        bool guard = (u == 0) | (u == RW - 1);
        if (!guard) {
            int gy = y0 - 12 + r;
            int gxb = x0 - 16 + 8 * (u - 1);
            bool rin = !BORDER || ((unsigned)gy < H);
            size_t rowoff = (size_t)gy * W;
            bool center = (u >= 3) & (u < 19) & (r >= 12) & (r < 12 + TY);
            unsigned tbits = 0;
            if (rin && (!BORDER || ((unsigned)gxb < W))) {
                float4 l = *(const float4*)(lg + rowoff + gxb);
                int4   t = *(const int4*)(tp + rowoff + gxb);
                float p0 = 1.0f / (1.0f + __expf(-l.x));
                float p1 = 1.0f / (1.0f + __expf(-l.y));
                float p2 = 1.0f / (1.0f + __expf(-l.z));
                float p3 = 1.0f / (1.0f + __expf(-l.w));
                vp.x = pack2(p0, p1); vp.y = pack2(p2, p3);
                tbits |= (unsigned)t.x | ((unsigned)t.y << 1) |
                         ((unsigned)t.z << 2) | ((unsigned)t.w << 3);
                if (center) {
                    s_inter += p0*(float)t.x + p1*(float)t.y + p2*(float)t.z + p3*(float)t.w;
                    s_cp += p0 + p1 + p2 + p3;
                    s_ct += (float)(t.x + t.y + t.z + t.w);
                }
            } else { vp.x = vp.y = PINF2; }
            if (rin && (!BORDER || ((unsigned)(gxb + 4) < W))) {
                float4 l = *(const float4*)(lg + rowoff + gxb + 4);
                int4   t = *(const int4*)(tp + rowoff + gxb + 4);
                float p0 = 1.0f / (1.0f + __expf(-l.x));
                float p1 = 1.0f / (1.0f + __expf(-l.y));
                float p2 = 1.0f / (1.0f + __expf(-l.z));
                float p3 = 1.0f / (1.0f + __expf(-l.w));
                vp.z = pack2(p0, p1); vp.w = pack2(p2, p3);
                tbits |= ((unsigned)t.x << 4) | ((unsigned)t.y << 5) |
                         ((unsigned)t.z << 6) | ((unsigned)t.w << 7);
                if (center) {
                    s_inter += p0*(float)t.x + p1*(float)t.y + p2*(float)t.z + p3*(float)t.w;
                    s_cp += p0 + p1 + p2 + p3;
                    s_ct += (float)(t.x + t.y + t.z + t.w);
                }
            } else { vp.z = vp.w = PINF2; }
            if (tbits) {
                int du = u - 1;
                atomicOr(&T0[r * BST + (du >> 2)], tbits << ((du & 3) * 8));
            }
        } else {
            vp = make_uint4(PINF2, PINF2, PINF2, PINF2);
            Bf[idx] = vp;
            Cf[idx] = vp;
        }
        A[idx] = vp;
    }
    __syncthreads();

    // ---- fp16 erode mapping: 20 cols x 22 groups x 4 rows (440 active)
    const int u1 = 1 + tid % 20;
    const int g1 = tid / 20;
    const int rs4 = 1 + 4 * g1;
    const bool g1ok = g1 < 22;
    bool xo0 = false, xo1 = false, xo2 = false, xo3 = false;
    if (BORDER) {
        int xb = x0 - 16 + 8 * (u1 - 1);
        xo0 = (unsigned)(xb + 0) >= W;
        xo1 = (unsigned)(xb + 2) >= W;
        xo2 = (unsigned)(xb + 4) >= W;
        xo3 = (unsigned)(xb + 6) >= W;
    }

    // ---- bit erode mapping: rows 1..86 x 5 words (430 active)
    const bool be_act = tid < (ROWS - 2) * BST;
    const int br = 1 + tid / BST;
    const int bw = tid % BST;
    const int bidx = br * BST + bw;
    unsigned be_nv = 0;
    if (BORDER && be_act) {
        int gy = y0 - 12 + br;
        unsigned V = ((unsigned)gy < H) ? xmask_f(x0 - 16 + 32 * bw) : 0u;
        be_nv = ~V;
    }

    // ---- fp16 dilate mapping: 16 cols x 32 groups x 2 rows (512 threads)
    const int u2 = 3 + (tid & 15);
    const int yb = 12 + 2 * (tid >> 4);

    // ---- bit dilate mapping: rows 12..75 x 5 words (320 active)
    const bool bd_act = tid < TY * BST;
    const int dr = 12 + tid / BST;
    const int dw2 = tid % BST;
    const int didx = dr * BST + dw2;
    unsigned m0 = ~0u, mm1 = ~0u, mp1 = ~0u;
    bool upok = true, dnok = true;
    if (BORDER && bd_act) {
        m0  = xmask_f(x0 - 16 + 32 * dw2);
        mm1 = (dw2 > 0) ? xmask_f(x0 - 16 + 32 * (dw2 - 1)) : 0u;
        mp1 = (dw2 < 4) ? xmask_f(x0 - 16 + 32 * (dw2 + 1)) : 0u;
        int gy = y0 - 12 + dr;
        upok = (gy - 1) >= 0;
        dnok = (gy + 1) < H;
    }
    unsigned skw = 0;

    float sk_o[16];
    #pragma unroll
    for (int i = 0; i < 16; i++) sk_o[i] = 0.f;

    // ---- software-pipelined 12-phase loop (one barrier per phase)
    uint4    *pF = Cf, *cF = A,  *nF = Bf;
    unsigned *pT = T2, *cT = T0, *nT = T1;

    for (int k = 0; k <= 11; k++) {
        if (k > 0) {
            // dilate of step k-1: av from E_{k-1}=pF, dilate input E_k=cF
            dilate_skel<BORDER>(pF, cF, u2, yb, sk_o);
            if (bd_act) {
                unsigned d = 0;
                #pragma unroll
                for (int rr = -1; rr <= 1; rr++) {
                    bool ok = (rr == -1) ? upok : ((rr == 1) ? dnok : true);
                    int bse = (dr + rr) * BST + dw2;
                    unsigned c  = cT[bse] & m0;
                    unsigned l  = (dw2 > 0) ? (cT[bse - 1] & mm1) : 0u;
                    unsigned rt = (dw2 < 4) ? (cT[bse + 1] & mp1) : 0u;
                    unsigned rowv = c | ((c << 1) | (l >> 31)) | ((c >> 1) | (rt << 31));
                    if (BORDER && !ok) rowv = 0u;
                    d |= rowv;
                }
                unsigned ecur = pT[didx] & m0;
                skw |= ecur & ~d;
            }
        }
        if (k < 11) {
            const int m = 11 - k;
            const int lo = 12 - m, hi = 12 + TY + m;
            int start = rs4 > lo ? rs4 : lo;
            int end   = (rs4 + 4 < hi) ? rs4 + 4 : hi;
            bool colact = (8 * (u1 - 1) < 144 + m) && (8 * u1 > 16 - m);
            if (g1ok && colact && start < end)
                erode_pass<BORDER>(cF, nF, u1, start, end, xo0, xo1, xo2, xo3, y0);
            if (be_act) {
                unsigned xc = cT[bidx];
                unsigned xu = cT[bidx - BST];
                unsigned xd = cT[bidx + BST];
                unsigned xl = (bw > 0) ? cT[bidx - 1] : ~0u;
                unsigned xr = (bw < 4) ? cT[bidx + 1] : ~0u;
                unsigned L = (xc << 1) | (xl >> 31);
                unsigned R = (xc >> 1) | (xr << 31);
                unsigned e = xc & xu & xd & L & R;
                if (BORDER) e |= be_nv;
                nT[bidx] = e;
            }
        }
        __syncthreads();
        uint4* t4; t4 = pF; pF = cF; cF = nF; nF = t4;
        unsigned* tb; tb = pT; pT = cT; cT = nT; nT = tb;
    }

    // ---- publish sk_t bits, cross-chain sums
    float s_st = 0.f;
    if (bd_act) {
        SK[didx] = skw;
        unsigned cmask = (dw2 == 0) ? 0xFFFF0000u : ((dw2 == 4) ? 0x0000FFFFu : ~0u);
        s_st = (float)__popc(skw & cmask);
    }
    __syncthreads();

    float sot = 0.f, so = 0.f;
    {
        const int du = u2 - 1;
        const int wd = du >> 2;
        const int bp = (du & 3) * 8;
        #pragma unroll
        for (int i = 0; i < 2; i++) {
            unsigned bbyte = (SK[(yb + i) * BST + wd] >> bp) & 0xffu;
            #pragma unroll
            for (int kk = 0; kk < 8; kk++) {
                float o = sk_o[i * 8 + kk];
                so += o;
                if ((bbyte >> kk) & 1u) sot += o;
            }
        }
    }

    float b;
    b = blockReduceSum(s_inter, red);      if (tid == 0) atomicAdd(&g_acc[0], (double)b);
    b = blockReduceSum(s_cp + s_ct, red);  if (tid == 0) atomicAdd(&g_acc[1], (double)b);
    b = blockReduceSum(s_ct, red);         if (tid == 0) atomicAdd(&g_acc[2], (double)b);
    b = blockReduceSum(sot, red);          if (tid == 0) atomicAdd(&g_acc[3], (double)b);
    b = blockReduceSum(so,  red);          if (tid == 0) atomicAdd(&g_acc[4], (double)b);
    b = blockReduceSum(s_st, red);         if (tid == 0) atomicAdd(&g_acc[5], (double)b);

    if (tid == 0) {
        __threadfence();
        unsigned done = atomicAdd(&g_done, 1u);
        if (done == NBLOCKS - 1) {
            double inter = atomicAdd(&g_acc[0], 0.0);
            double card  = atomicAdd(&g_acc[1], 0.0);
            double sumt  = atomicAdd(&g_acc[2], 0.0);
            double sot2  = atomicAdd(&g_acc[3], 0.0);
            double so2   = atomicAdd(&g_acc[4], 0.0);
            double stk   = atomicAdd(&g_acc[5], 0.0);
            double score = (2.0 * inter + 1.0) / fmax(card + 1.0, 1e-7);
            double dice  = (1.0 - score) * (sumt > 0.0 ? 1.0 : 0.0);
            double tprec = (sot2 + 1.0) / (so2 + 1.0);
            double tsens = (sot2 + 1.0) / (stk + 1.0);
            double cs    = 2.0 * (tprec * tsens) / (tprec + tsens);
            double cl    = (1.0 - cs) * (stk > 0.0 ? 1.0 : 0.0);
            out[0] = (float)(0.5 * dice + 0.5 * cl);
            g_acc[0] = 0.0; g_acc[1] = 0.0; g_acc[2] = 0.0;
            g_acc[3] = 0.0; g_acc[4] = 0.0; g_acc[5] = 0.0;
            __threadfence();
            g_done = 0;
        }
    }
}

// ---------------------------------------------------------------------------
__global__ void __launch_bounds__(NT, 2)
fused_kernel(const float* __restrict__ logits, const int* __restrict__ target,
             float* __restrict__ out)
{
    extern __shared__ uint4 smem4[];
    __shared__ float red[32];
    uint4* A  = smem4;
    uint4* Bf = A + BUF_U4;
    uint4* Cf = Bf + BUF_U4;
    unsigned* bits = (unsigned*)(Cf + BUF_U4);
    unsigned* T0 = bits;
    unsigned* T1 = bits + BBUF;
    unsigned* T2 = bits + 2 * BBUF;
    unsigned* SK = bits + 3 * BBUF;
    bool border = (blockIdx.x == 0) | (blockIdx.x == gridDim.x - 1) |
                  (blockIdx.y == 0) | (blockIdx.y == gridDim.y - 1);
    if (border) tile_run<true >(logits, target, A, Bf, Cf, T0, T1, T2, SK, red, out);
    else        tile_run<false>(logits, target, A, Bf, Cf, T0, T1, T2, SK, red, out);
}

// ---------------------------------------------------------------------------
extern "C" void kernel_launch(void* const* d_in, const int* in_sizes, int n_in,
                              void* d_out, int out_size) {
    (void)in_sizes; (void)n_in; (void)out_size;
    const float* logits = (const float*)d_in[0];
    const int*   target = (const int*)d_in[1];

    const int smem_bytes = 3 * BUF_U4 * (int)sizeof(uint4) + 4 * BBUF * (int)sizeof(unsigned);
    cudaFuncSetAttribute(fused_kernel,
                         cudaFuncAttributeMaxDynamicSharedMemorySize, smem_bytes);

    dim3 grid(W / TX, H / TY, 8);
    fused_kernel<<<grid, NT, smem_bytes>>>(logits, target, (float*)d_out);
}

// round 8
// speedup vs baseline: 5.0453x; 1.0342x over previous
#include <cuda_runtime.h>
#include <cuda_fp16.h>

#define H 1024
#define W 1024
#define PLANE_SZ (H * W)

#define TX 128
#define TY 64
#define NT 512
#define ROWS (TY + 24)         // 88
#define RW 22                  // uint4 per row: 20 data + 2 guards
#define BUF_U4 (ROWS * RW)
#define PINF2 0x7C007C00u
#define ONE2  0x3C003C00u
#define NBLOCKS 1024

#define BST 5
#define BBUF (ROWS * BST)

__device__ double g_acc[6];
__device__ unsigned g_done;

// ---------------------------------------------------------------------------
__device__ __forceinline__ unsigned hmin2u(unsigned a, unsigned b) {
    __half2 r = __hmin2(*(__half2*)&a, *(__half2*)&b);
    return *(unsigned*)&r;
}
__device__ __forceinline__ unsigned hmax2u(unsigned a, unsigned b) {
    __half2 r = __hmax2(*(__half2*)&a, *(__half2*)&b);
    return *(unsigned*)&r;
}
__device__ __forceinline__ unsigned hsub2u(unsigned a, unsigned b) {
    __half2 r = __hsub2(*(__half2*)&a, *(__half2*)&b);
    return *(unsigned*)&r;
}
__device__ __forceinline__ unsigned hfma2u(unsigned a, unsigned b, unsigned c) {
    __half2 r = __hfma2(*(__half2*)&a, *(__half2*)&b, *(__half2*)&c);
    return *(unsigned*)&r;
}
__device__ __forceinline__ unsigned pack2(float a, float b) {
    __half2 h = __floats2half2_rn(a, b);
    return *(unsigned*)&h;
}
__device__ __forceinline__ float2 unpack2(unsigned v) {
    return __half22float2(*(__half2*)&v);
}
__device__ __forceinline__ unsigned remap2u(unsigned v) {
    unsigned m = __vcmpeq2(v, PINF2) & 0x80008000u;
    return v | m;
}
__device__ __forceinline__ unsigned xmask_f(int startpx) {
    unsigned m = ~0u;
    if (startpx < 0) { int k = -startpx; m = (k >= 32) ? 0u : (m << k); }
    int k2 = startpx + 32 - W;
    if (k2 > 0) m &= (k2 >= 32) ? 0u : (~0u >> k2);
    return m;
}

__device__ __forceinline__ float blockReduceSum(float v, float* red) {
    #pragma unroll
    for (int o = 16; o > 0; o >>= 1) v += __shfl_down_sync(0xffffffffu, v, o);
    int lane = threadIdx.x & 31;
    int wid  = threadIdx.x >> 5;
    if (lane == 0) red[wid] = v;
    __syncthreads();
    v = (threadIdx.x < 16) ? red[threadIdx.x] : 0.0f;
    if (wid == 0) {
        #pragma unroll
        for (int o = 8; o > 0; o >>= 1) v += __shfl_down_sync(0xffffffffu, v, o);
    }
    __syncthreads();
    return v;
}

// ---------------------------------------------------------------------------
template<bool BORDER>
__device__ __forceinline__ void erode_pass(const uint4* __restrict__ cur,
                                           uint4* __restrict__ nxt,
                                           int u1, int start, int end,
                                           bool xo0, bool xo1, bool xo2, bool xo3,
                                           int y0)
{
    const unsigned* cur32 = (const unsigned*)cur;
    int base = start * RW + u1;
    uint4 a = cur[base - RW];
    uint4 b = cur[base];
    for (int r = start; r < end; r++) {
        uint4 c = cur[base + RW];
        unsigned Lh = cur32[4 * base - 1];
        unsigned Rh = cur32[4 * base + 4];
        unsigned P0 = __byte_perm(Lh,  b.x, 0x5432);
        unsigned P1 = __byte_perm(b.x, b.y, 0x5432);
        unsigned P2 = __byte_perm(b.y, b.z, 0x5432);
        unsigned P3 = __byte_perm(b.z, b.w, 0x5432);
        unsigned P4 = __byte_perm(b.w, Rh, 0x5432);
        uint4 e;
        e.x = hmin2u(hmin2u(a.x, c.x), hmin2u(b.x, hmin2u(P0, P1)));
        e.y = hmin2u(hmin2u(a.y, c.y), hmin2u(b.y, hmin2u(P1, P2)));
        e.z = hmin2u(hmin2u(a.z, c.z), hmin2u(b.z, hmin2u(P2, P3)));
        e.w = hmin2u(hmin2u(a.w, c.w), hmin2u(b.w, hmin2u(P3, P4)));
        if (BORDER) {
            bool yo = ((unsigned)(y0 - 12 + r) >= H);
            if (xo0 | yo) e.x = PINF2;
            if (xo1 | yo) e.y = PINF2;
            if (xo2 | yo) e.z = PINF2;
            if (xo3 | yo) e.w = PINF2;
        }
        nxt[base] = e;
        a = b; b = c; base += RW;
    }
}

template<bool BORDER>
__device__ __forceinline__ uint4 rowmax_fn(const uint4* __restrict__ nxt,
                                           const unsigned* __restrict__ nxt32,
                                           int base)
{
    uint4 C = nxt[base];
    unsigned Lh = nxt32[4 * base - 1];
    unsigned Rh = nxt32[4 * base + 4];
    if (BORDER) {
        C.x = remap2u(C.x); C.y = remap2u(C.y); C.z = remap2u(C.z); C.w = remap2u(C.w);
        Lh = remap2u(Lh); Rh = remap2u(Rh);
    }
    unsigned P0 = __byte_perm(Lh,  C.x, 0x5432);
    unsigned P1 = __byte_perm(C.x, C.y, 0x5432);
    unsigned P2 = __byte_perm(C.y, C.z, 0x5432);
    unsigned P3 = __byte_perm(C.z, C.w, 0x5432);
    unsigned P4 = __byte_perm(C.w, Rh, 0x5432);
    uint4 h;
    h.x = hmax2u(C.x, hmax2u(P0, P1));
    h.y = hmax2u(C.y, hmax2u(P1, P2));
    h.z = hmax2u(C.z, hmax2u(P2, P3));
    h.w = hmax2u(C.w, hmax2u(P3, P4));
    return h;
}

// dilate 3x3 of dil, u *= (1 - relu(av - d)) via hfma2(u, min(d-av,0), u)
template<bool BORDER>
__device__ __forceinline__ void dilate_skel(const uint4* __restrict__ av_buf,
                                            const uint4* __restrict__ dil,
                                            int u2, int yb, unsigned* uacc)
{
    const unsigned* dil32 = (const unsigned*)dil;
    uint4 h0 = rowmax_fn<BORDER>(dil, dil32, (yb - 1) * RW + u2);
    uint4 h1 = rowmax_fn<BORDER>(dil, dil32,  yb      * RW + u2);
    #pragma unroll
    for (int i = 0; i < 2; i++) {
        uint4 h2 = rowmax_fn<BORDER>(dil, dil32, (yb + 1 + i) * RW + u2);
        uint4 av = av_buf[(yb + i) * RW + u2];
        unsigned dw, nd;

        dw = hmax2u(h0.x, hmax2u(h1.x, h2.x));
        nd = hmin2u(hsub2u(dw, av.x), 0u);
        uacc[i*4+0] = hfma2u(uacc[i*4+0], nd, uacc[i*4+0]);

        dw = hmax2u(h0.y, hmax2u(h1.y, h2.y));
        nd = hmin2u(hsub2u(dw, av.y), 0u);
        uacc[i*4+1] = hfma2u(uacc[i*4+1], nd, uacc[i*4+1]);

        dw = hmax2u(h0.z, hmax2u(h1.z, h2.z));
        nd = hmin2u(hsub2u(dw, av.z), 0u);
        uacc[i*4+2] = hfma2u(uacc[i*4+2], nd, uacc[i*4+2]);

        dw = hmax2u(h0.w, hmax2u(h1.w, h2.w));
        nd = hmin2u(hsub2u(dw, av.w), 0u);
        uacc[i*4+3] = hfma2u(uacc[i*4+3], nd, uacc[i*4+3]);

        h0 = h1; h1 = h2;
    }
}

// ---------------------------------------------------------------------------
template<bool BORDER>
__device__ __forceinline__ void tile_run(const float* __restrict__ logits,
                                         const int* __restrict__ target,
                                         uint4* A, uint4* Bf, uint4* Cf,
                                         unsigned* T0, unsigned* T1, unsigned* T2,
                                         unsigned* SK,
                                         float* red, float* out)
{
    const int p8 = blockIdx.z;
    const int x0 = blockIdx.x * TX;
    const int y0 = blockIdx.y * TY;
    const int tid = threadIdx.x;
    const float* lg = logits + (size_t)p8 * PLANE_SZ;
    const int*   tp = target + (size_t)p8 * PLANE_SZ;

    if (tid < BBUF) {
        int r = tid / BST, w = tid - r * BST;
        unsigned V;
        if (BORDER) {
            int gy = y0 - 12 + r;
            V = ((unsigned)gy < H) ? xmask_f(x0 - 16 + 32 * w) : 0u;
        } else V = ~0u;
        T0[tid] = ~V;
    }
    __syncthreads();

    float s_inter = 0.f, s_cp = 0.f, s_ct = 0.f;
    for (int idx = tid; idx < BUF_U4; idx += NT) {
        int r = idx / RW;
        int u = idx - r * RW;
        uint4 vp;
        bool guard = (u == 0) | (u == RW - 1);
        if (!guard) {
            int gy = y0 - 12 + r;
            int gxb = x0 - 16 + 8 * (u - 1);
            bool rin = !BORDER || ((unsigned)gy < H);
            size_t rowoff = (size_t)gy * W;
            bool center = (u >= 3) & (u < 19) & (r >= 12) & (r < 12 + TY);
            unsigned tbits = 0;
            if (rin && (!BORDER || ((unsigned)gxb < W))) {
                float4 l = *(const float4*)(lg + rowoff + gxb);
                int4   t = *(const int4*)(tp + rowoff + gxb);
                float p0 = 1.0f / (1.0f + __expf(-l.x));
                float p1 = 1.0f / (1.0f + __expf(-l.y));
                float p2 = 1.0f / (1.0f + __expf(-l.z));
                float p3 = 1.0f / (1.0f + __expf(-l.w));
                vp.x = pack2(p0, p1); vp.y = pack2(p2, p3);
                tbits |= (unsigned)t.x | ((unsigned)t.y << 1) |
                         ((unsigned)t.z << 2) | ((unsigned)t.w << 3);
                if (center) {
                    s_inter += p0*(float)t.x + p1*(float)t.y + p2*(float)t.z + p3*(float)t.w;
                    s_cp += p0 + p1 + p2 + p3;
                    s_ct += (float)(t.x + t.y + t.z + t.w);
                }
            } else { vp.x = vp.y = PINF2; }
            if (rin && (!BORDER || ((unsigned)(gxb + 4) < W))) {
                float4 l = *(const float4*)(lg + rowoff + gxb + 4);
                int4   t = *(const int4*)(tp + rowoff + gxb + 4);
                float p0 = 1.0f / (1.0f + __expf(-l.x));
                float p1 = 1.0f / (1.0f + __expf(-l.y));
                float p2 = 1.0f / (1.0f + __expf(-l.z));
                float p3 = 1.0f / (1.0f + __expf(-l.w));
                vp.z = pack2(p0, p1); vp.w = pack2(p2, p3);
                tbits |= ((unsigned)t.x << 4) | ((unsigned)t.y << 5) |
                         ((unsigned)t.z << 6) | ((unsigned)t.w << 7);
                if (center) {
                    s_inter += p0*(float)t.x + p1*(float)t.y + p2*(float)t.z + p3*(float)t.w;
                    s_cp += p0 + p1 + p2 + p3;
                    s_ct += (float)(t.x + t.y + t.z + t.w);
                }
            } else { vp.z = vp.w = PINF2; }
            if (tbits) {
                int du = u - 1;
                atomicOr(&T0[r * BST + (du >> 2)], tbits << ((du & 3) * 8));
            }
        } else {
            vp = make_uint4(PINF2, PINF2, PINF2, PINF2);
            Bf[idx] = vp;
            Cf[idx] = vp;
        }
        A[idx] = vp;
    }
    __syncthreads();

    const int u1 = 1 + tid % 20;
    const int g1 = tid / 20;
    const int rs4 = 1 + 4 * g1;
    const bool g1ok = g1 < 22;
    bool xo0 = false, xo1 = false, xo2 = false, xo3 = false;
    if (BORDER) {
        int xb = x0 - 16 + 8 * (u1 - 1);
        xo0 = (unsigned)(xb + 0) >= W;
        xo1 = (unsigned)(xb + 2) >= W;
        xo2 = (unsigned)(xb + 4) >= W;
        xo3 = (unsigned)(xb + 6) >= W;
    }

    const bool be_act = tid < (ROWS - 2) * BST;
    const int br = 1 + tid / BST;
    const int bw = tid % BST;
    const int bidx = br * BST + bw;
    unsigned be_nv = 0;
    if (BORDER && be_act) {
        int gy = y0 - 12 + br;
        unsigned V = ((unsigned)gy < H) ? xmask_f(x0 - 16 + 32 * bw) : 0u;
        be_nv = ~V;
    }

    const int u2 = 3 + (tid & 15);
    const int yb = 12 + 2 * (tid >> 4);

    const bool bd_act = tid < TY * BST;
    const int dr = 12 + tid / BST;
    const int dw2 = tid % BST;
    const int didx = dr * BST + dw2;
    unsigned m0 = ~0u, mm1 = ~0u, mp1 = ~0u;
    bool upok = true, dnok = true;
    if (BORDER && bd_act) {
        m0  = xmask_f(x0 - 16 + 32 * dw2);
        mm1 = (dw2 > 0) ? xmask_f(x0 - 16 + 32 * (dw2 - 1)) : 0u;
        mp1 = (dw2 < 4) ? xmask_f(x0 - 16 + 32 * (dw2 + 1)) : 0u;
        int gy = y0 - 12 + dr;
        upok = (gy - 1) >= 0;
        dnok = (gy + 1) < H;
    }
    unsigned skw = 0;

    unsigned uacc[8];   // u = 1 - sk, as half2 (2 px each)
    #pragma unroll
    for (int i = 0; i < 8; i++) uacc[i] = ONE2;

    uint4    *pF = Cf, *cF = A,  *nF = Bf;
    unsigned *pT = T2, *cT = T0, *nT = T1;

    for (int k = 0; k <= 11; k++) {
        if (k > 0) {
            dilate_skel<BORDER>(pF, cF, u2, yb, uacc);
            if (bd_act) {
                unsigned d = 0;
                #pragma unroll
                for (int rr = -1; rr <= 1; rr++) {
                    bool ok = (rr == -1) ? upok : ((rr == 1) ? dnok : true);
                    int bse = (dr + rr) * BST + dw2;
                    unsigned c  = cT[bse] & m0;
                    unsigned l  = (dw2 > 0) ? (cT[bse - 1] & mm1) : 0u;
                    unsigned rt = (dw2 < 4) ? (cT[bse + 1] & mp1) : 0u;
                    unsigned rowv = c | ((c << 1) | (l >> 31)) | ((c >> 1) | (rt << 31));
                    if (BORDER && !ok) rowv = 0u;
                    d |= rowv;
                }
                unsigned ecur = pT[didx] & m0;
                skw |= ecur & ~d;
            }
        }
        if (k < 11) {
            const int m = 11 - k;
            const int lo = 12 - m, hi = 12 + TY + m;
            int start = rs4 > lo ? rs4 : lo;
            int end   = (rs4 + 4 < hi) ? rs4 + 4 : hi;
            bool colact = (8 * (u1 - 1) < 144 + m) && (8 * u1 > 16 - m);
            if (g1ok && colact && start < end)
                erode_pass<BORDER>(cF, nF, u1, start, end, xo0, xo1, xo2, xo3, y0);
            if (be_act) {
                unsigned xc = cT[bidx];
                unsigned xu = cT[bidx - BST];
                unsigned xd = cT[bidx + BST];
                unsigned xl = (bw > 0) ? cT[bidx - 1] : ~0u;
                unsigned xr = (bw < 4) ? cT[bidx + 1] : ~0u;
                unsigned L = (xc << 1) | (xl >> 31);
                unsigned R = (xc >> 1) | (xr << 31);
                unsigned e = xc & xu & xd & L & R;
                if (BORDER) e |= be_nv;
                nT[bidx] = e;
            }
        }
        __syncthreads();
        uint4* t4; t4 = pF; pF = cF; cF = nF; nF = t4;
        unsigned* tb; tb = pT; pT = cT; cT = nT; nT = tb;
    }

    float s_st = 0.f;
    if (bd_act) {
        SK[didx] = skw;
        unsigned cmask = (dw2 == 0) ? 0xFFFF0000u : ((dw2 == 4) ? 0x0000FFFFu : ~0u);
        s_st = (float)__popc(skw & cmask);
    }
    __syncthreads();

    float sot = 0.f, so = 0.f;
    {
        const int du = u2 - 1;
        const int wd = du >> 2;
        const int bp = (du & 3) * 8;
        #pragma unroll
        for (int i = 0; i < 2; i++) {
            unsigned bbyte = (SK[(yb + i) * BST + wd] >> bp) & 0xffu;
            #pragma unroll
            for (int j = 0; j < 4; j++) {
                float2 f = unpack2(uacc[i * 4 + j]);
                float sx = 1.0f - f.x;
                float sy = 1.0f - f.y;
                so += sx + sy;
                if ((bbyte >> (2 * j)) & 1u)     sot += sx;
                if ((bbyte >> (2 * j + 1)) & 1u) sot += sy;
            }
        }
    }

    float b;
    b = blockReduceSum(s_inter, red);      if (tid == 0) atomicAdd(&g_acc[0], (double)b);
    b = blockReduceSum(s_cp + s_ct, red);  if (tid == 0) atomicAdd(&g_acc[1], (double)b);
    b = blockReduceSum(s_ct, red);         if (tid == 0) atomicAdd(&g_acc[2], (double)b);
    b = blockReduceSum(sot, red);          if (tid == 0) atomicAdd(&g_acc[3], (double)b);
    b = blockReduceSum(so,  red);          if (tid == 0) atomicAdd(&g_acc[4], (double)b);
    b = blockReduceSum(s_st, red);         if (tid == 0) atomicAdd(&g_acc[5], (double)b);

    if (tid == 0) {
        __threadfence();
        unsigned done = atomicAdd(&g_done, 1u);
        if (done == NBLOCKS - 1) {
            double inter = atomicAdd(&g_acc[0], 0.0);
            double card  = atomicAdd(&g_acc[1], 0.0);
            double sumt  = atomicAdd(&g_acc[2], 0.0);
            double sot2  = atomicAdd(&g_acc[3], 0.0);
            double so2   = atomicAdd(&g_acc[4], 0.0);
            double stk   = atomicAdd(&g_acc[5], 0.0);
            double score = (2.0 * inter + 1.0) / fmax(card + 1.0, 1e-7);
            double dice  = (1.0 - score) * (sumt > 0.0 ? 1.0 : 0.0);
            double tprec = (sot2 + 1.0) / (so2 + 1.0);
            double tsens = (sot2 + 1.0) / (stk + 1.0);
            double cs    = 2.0 * (tprec * tsens) / (tprec + tsens);
            double cl    = (1.0 - cs) * (stk > 0.0 ? 1.0 : 0.0);
            out[0] = (float)(0.5 * dice + 0.5 * cl);
            g_acc[0] = 0.0; g_acc[1] = 0.0; g_acc[2] = 0.0;
            g_acc[3] = 0.0; g_acc[4] = 0.0; g_acc[5] = 0.0;
            __threadfence();
            g_done = 0;
        }
    }
}

// ---------------------------------------------------------------------------
__global__ void __launch_bounds__(NT, 2)
fused_kernel(const float* __restrict__ logits, const int* __restrict__ target,
             float* __restrict__ out)
{
    extern __shared__ uint4 smem4[];
    __shared__ float red[32];
    uint4* A  = smem4;
    uint4* Bf = A + BUF_U4;
    uint4* Cf = Bf + BUF_U4;
    unsigned* bits = (unsigned*)(Cf + BUF_U4);
    unsigned* T0 = bits;
    unsigned* T1 = bits + BBUF;
    unsigned* T2 = bits + 2 * BBUF;
    unsigned* SK = bits + 3 * BBUF;
    bool border = (blockIdx.x == 0) | (blockIdx.x == gridDim.x - 1) |
                  (blockIdx.y == 0) | (blockIdx.y == gridDim.y - 1);
    if (border) tile_run<true >(logits, target, A, Bf, Cf, T0, T1, T2, SK, red, out);
    else        tile_run<false>(logits, target, A, Bf, Cf, T0, T1, T2, SK, red, out);
}

// ---------------------------------------------------------------------------
extern "C" void kernel_launch(void* const* d_in, const int* in_sizes, int n_in,
                              void* d_out, int out_size) {
    (void)in_sizes; (void)n_in; (void)out_size;
    const float* logits = (const float*)d_in[0];
    const int*   target = (const int*)d_in[1];

    const int smem_bytes = 3 * BUF_U4 * (int)sizeof(uint4) + 4 * BBUF * (int)sizeof(unsigned);
    cudaFuncSetAttribute(fused_kernel,
                         cudaFuncAttributeMaxDynamicSharedMemorySize, smem_bytes);

    dim3 grid(W / TX, H / TY, 8);
    fused_kernel<<<grid, NT, smem_bytes>>>(logits, target, (float*)d_out);
}